// round 4
// baseline (speedup 1.0000x reference)
#include <cuda_runtime.h>
#include <math.h>
#include <stdint.h>

// Problem constants
#define PB 2
#define PN 2048
#define PE 1024
#define PH 16
#define PD 64
#define M_TOK (PB * PN)        // 4096 tokens
#define QKV_COLS (3 * PE)      // 3072

// Scratch (no cudaMalloc allowed)
__device__ float g_Q[PB * PH * PN * PD];   // [B,H,N,D]
__device__ float g_K[PB * PH * PN * PD];
__device__ float g_V[PB * PH * PN * PD];
__device__ float g_O[M_TOK * PE];          // [B,N,E] pre-projection

// ---------------------------------------------------------------------------
// SGEMM NT: C[M,Ncols] = A[M,K] * Bm[Ncols,K]^T (+bias)
// BM=BN=128, BK=16, 256 threads, 8x8 per thread (2x2 blocks of 4x4).
// EPI 0: scatter into g_Q/g_K/g_V with bias. EPI 1: plain store + bias.
// ---------------------------------------------------------------------------
template <int EPI>
__global__ __launch_bounds__(256, 2)
void sgemm_nt(const float* __restrict__ A, const float* __restrict__ Bm,
              const float* __restrict__ bias, float* __restrict__ C,
              int M, int Ncols, int K)
{
    __shared__ float As[16][132];
    __shared__ float Bs[16][132];

    const int tid = threadIdx.x;
    const int tx = tid & 15;
    const int ty = tid >> 4;
    const int m0 = blockIdx.y * 128;
    const int n0 = blockIdx.x * 128;

    float acc[8][8];
#pragma unroll
    for (int i = 0; i < 8; i++)
#pragma unroll
        for (int j = 0; j < 8; j++) acc[i][j] = 0.f;

    for (int kt = 0; kt < K; kt += 16) {
#pragma unroll
        for (int e = 0; e < 2; e++) {
            int idx = tid + e * 256;      // 0..511 float4 slots
            int row = idx >> 2;           // 0..127
            int kq  = (idx & 3) << 2;     // 0,4,8,12
            float4 a = *(const float4*)(A + (size_t)(m0 + row) * K + kt + kq);
            As[kq + 0][row] = a.x; As[kq + 1][row] = a.y;
            As[kq + 2][row] = a.z; As[kq + 3][row] = a.w;
            float4 b = *(const float4*)(Bm + (size_t)(n0 + row) * K + kt + kq);
            Bs[kq + 0][row] = b.x; Bs[kq + 1][row] = b.y;
            Bs[kq + 2][row] = b.z; Bs[kq + 3][row] = b.w;
        }
        __syncthreads();
#pragma unroll
        for (int kk = 0; kk < 16; kk++) {
            float a[8], b[8];
            *(float4*)(a + 0) = *(const float4*)&As[kk][4 * ty];
            *(float4*)(a + 4) = *(const float4*)&As[kk][64 + 4 * ty];
            *(float4*)(b + 0) = *(const float4*)&Bs[kk][4 * tx];
            *(float4*)(b + 4) = *(const float4*)&Bs[kk][64 + 4 * tx];
#pragma unroll
            for (int i = 0; i < 8; i++)
#pragma unroll
                for (int j = 0; j < 8; j++) acc[i][j] += a[i] * b[j];
        }
        __syncthreads();
    }

    // Epilogue
#pragma unroll
    for (int bi = 0; bi < 2; bi++) {
#pragma unroll
        for (int i = 0; i < 4; i++) {
            int row = m0 + bi * 64 + 4 * ty + i;  // token index
#pragma unroll
            for (int bj = 0; bj < 2; bj++) {
                if (EPI == 1) {
                    int col = n0 + bj * 64 + 4 * tx;
                    float4 v;
                    v.x = acc[bi * 4 + i][bj * 4 + 0] + bias[col + 0];
                    v.y = acc[bi * 4 + i][bj * 4 + 1] + bias[col + 1];
                    v.z = acc[bi * 4 + i][bj * 4 + 2] + bias[col + 2];
                    v.w = acc[bi * 4 + i][bj * 4 + 3] + bias[col + 3];
                    *(float4*)(C + (size_t)row * Ncols + col) = v;
                } else {
#pragma unroll
                    for (int j = 0; j < 4; j++) {
                        int col = n0 + bj * 64 + 4 * tx + j;
                        float v = acc[bi * 4 + i][bj * 4 + j] + bias[col];
                        // col = h*(D*3) + d*3 + which  (qkv index innermost)
                        int which = col % 3;
                        int rest  = col / 3;          // h*64 + d
                        int h = rest >> 6;
                        int d = rest & 63;
                        int bb = row >> 11;           // / 2048
                        int n  = row & 2047;
                        size_t dst = (((size_t)(bb * PH + h)) * PN + n) * PD + d;
                        float* out = (which == 0) ? g_Q : (which == 1) ? g_K : g_V;
                        out[dst] = v;
                    }
                }
            }
        }
    }
}

// ---------------------------------------------------------------------------
// Flash attention, fp32. Br=Bc=64, 256 threads (16x16), online softmax.
// smem: Qs[64][64] | KP[64][65] (K tile, later reused for P) | Vs[64][64]
// ---------------------------------------------------------------------------
__global__ __launch_bounds__(256)
void flash_attn(const float* __restrict__ Qg, const float* __restrict__ Kg,
                const float* __restrict__ Vg, float* __restrict__ Og)
{
    extern __shared__ float sm[];
    float* Qs = sm;                 // 4096 floats
    float* KP = sm + 64 * 64;       // 4160 floats (stride 65)
    float* Vs = KP + 64 * 65;       // 4096 floats

    const int tid = threadIdx.x;
    const int tx = tid & 15;
    const int ty = tid >> 4;
    const int bh = blockIdx.y;          // b*H + h
    const int n0 = blockIdx.x * 64;     // query tile start
    const size_t base = (size_t)bh * PN * PD;
    const float scale = 0.125f;         // 1/sqrt(64)

    // Load Q tile (row-major, d contiguous)
    for (int idx = tid; idx < 64 * 64; idx += 256) {
        int r = idx >> 6, d = idx & 63;
        Qs[r * 64 + d] = Qg[base + (size_t)(n0 + r) * PD + d];
    }

    float o[4][4];
    float m_i[4], l_i[4];
#pragma unroll
    for (int i = 0; i < 4; i++) {
        m_i[i] = -INFINITY; l_i[i] = 0.f;
#pragma unroll
        for (int j = 0; j < 4; j++) o[i][j] = 0.f;
    }
    __syncthreads();

    for (int kt = 0; kt < PN / 64; kt++) {
        int k0 = kt * 64;
        for (int idx = tid; idx < 64 * 64; idx += 256) {
            int r = idx >> 6, d = idx & 63;
            KP[r * 65 + d] = Kg[base + (size_t)(k0 + r) * PD + d];
            Vs[r * 64 + d] = Vg[base + (size_t)(k0 + r) * PD + d];
        }
        __syncthreads();

        // S = Q K^T  (each thread: rows 4ty+i, cols 4tx+j)
        float s[4][4];
#pragma unroll
        for (int i = 0; i < 4; i++)
#pragma unroll
            for (int j = 0; j < 4; j++) s[i][j] = 0.f;

        for (int k = 0; k < 64; k += 4) {
            float q[4][4];
#pragma unroll
            for (int i = 0; i < 4; i++) {
                float4 t = *(const float4*)&Qs[(4 * ty + i) * 64 + k];
                q[i][0] = t.x; q[i][1] = t.y; q[i][2] = t.z; q[i][3] = t.w;
            }
#pragma unroll
            for (int kk = 0; kk < 4; kk++) {
                float kv[4];
#pragma unroll
                for (int j = 0; j < 4; j++)
                    kv[j] = KP[(4 * tx + j) * 65 + k + kk];
#pragma unroll
                for (int i = 0; i < 4; i++)
#pragma unroll
                    for (int j = 0; j < 4; j++)
                        s[i][j] += q[i][kk] * kv[j];
            }
        }

        // Online softmax (row reductions across the 16 tx lanes)
        float mnew[4], alpha[4];
#pragma unroll
        for (int i = 0; i < 4; i++) {
            float mt = s[i][0];
#pragma unroll
            for (int j = 1; j < 4; j++) mt = fmaxf(mt, s[i][j]);
            mt *= scale;
#pragma unroll
            for (int off = 8; off >= 1; off >>= 1)
                mt = fmaxf(mt, __shfl_xor_sync(0xffffffffu, mt, off));
            mnew[i] = fmaxf(m_i[i], mt);
            alpha[i] = __expf(m_i[i] - mnew[i]);
            m_i[i] = mnew[i];
        }
        float p[4][4];
#pragma unroll
        for (int i = 0; i < 4; i++) {
            float lt = 0.f;
#pragma unroll
            for (int j = 0; j < 4; j++) {
                p[i][j] = __expf(s[i][j] * scale - mnew[i]);
                lt += p[i][j];
            }
#pragma unroll
            for (int off = 8; off >= 1; off >>= 1)
                lt += __shfl_xor_sync(0xffffffffu, lt, off);
            l_i[i] = l_i[i] * alpha[i] + lt;
#pragma unroll
            for (int j = 0; j < 4; j++) o[i][j] *= alpha[i];
        }

        __syncthreads();          // all KP reads done
#pragma unroll
        for (int i = 0; i < 4; i++)
#pragma unroll
            for (int j = 0; j < 4; j++)
                KP[(4 * ty + i) * 65 + 4 * tx + j] = p[i][j];
        __syncthreads();          // P visible

        // O += P V  (each thread: rows 4ty+i, d-cols 4tx+j)
        for (int jj = 0; jj < 64; jj++) {
            float pv[4];
#pragma unroll
            for (int i = 0; i < 4; i++) pv[i] = KP[(4 * ty + i) * 65 + jj];
            float4 vv = *(const float4*)&Vs[jj * 64 + 4 * tx];
#pragma unroll
            for (int i = 0; i < 4; i++) {
                o[i][0] += pv[i] * vv.x;
                o[i][1] += pv[i] * vv.y;
                o[i][2] += pv[i] * vv.z;
                o[i][3] += pv[i] * vv.w;
            }
        }
        __syncthreads();          // before overwriting KP/Vs next iter
    }

    // Epilogue: O[b, n, h*64+d] = o / l
    int b = bh / PH, h = bh % PH;
#pragma unroll
    for (int i = 0; i < 4; i++) {
        float inv_l = 1.f / l_i[i];
        int n = n0 + 4 * ty + i;
        float4 v;
        v.x = o[i][0] * inv_l; v.y = o[i][1] * inv_l;
        v.z = o[i][2] * inv_l; v.w = o[i][3] * inv_l;
        *(float4*)&g_O[((size_t)b * PN + n) * PE + h * 64 + 4 * tx] = v;
    }
    (void)Og;
}

// ---------------------------------------------------------------------------
extern "C" void kernel_launch(void* const* d_in, const int* in_sizes, int n_in,
                              void* d_out, int out_size)
{
    const float* x      = (const float*)d_in[0];
    const float* w_qkv  = (const float*)d_in[1];
    const float* b_qkv  = (const float*)d_in[2];
    const float* w_proj = (const float*)d_in[3];
    const float* b_proj = (const float*)d_in[4];
    float* out = (float*)d_out;

    // 1) QKV projection + scatter
    {
        dim3 grid(QKV_COLS / 128, M_TOK / 128);
        sgemm_nt<0><<<grid, 256>>>(x, w_qkv, b_qkv, nullptr, M_TOK, QKV_COLS, PE);
    }

    // 2) Flash attention
    {
        static int smem_set = 0;
        const int smem = (64 * 64 + 64 * 65 + 64 * 64) * sizeof(float); // 49408
        if (!smem_set) {
            cudaFuncSetAttribute(flash_attn,
                                 cudaFuncAttributeMaxDynamicSharedMemorySize, smem);
            smem_set = 1;
        }
        dim3 grid(PN / 64, PB * PH);
        float *Qp, *Kp, *Vp, *Op;
        cudaGetSymbolAddress((void**)&Qp, g_Q);
        cudaGetSymbolAddress((void**)&Kp, g_K);
        cudaGetSymbolAddress((void**)&Vp, g_V);
        cudaGetSymbolAddress((void**)&Op, g_O);
        flash_attn<<<grid, 256, smem>>>(Qp, Kp, Vp, Op);
    }

    // 3) Output projection
    {
        float* Op;
        cudaGetSymbolAddress((void**)&Op, g_O);
        dim3 grid(PE / 128, M_TOK / 128);
        sgemm_nt<1><<<grid, 256>>>(Op, w_proj, b_proj, out, M_TOK, PE, PE);
    }
}

// round 6
// speedup vs baseline: 1.4586x; 1.4586x over previous
#include <cuda_runtime.h>
#include <math.h>
#include <stdint.h>

// Problem constants
#define PB 2
#define PN 2048
#define PE 1024
#define PH 16
#define PD 64
#define M_TOK (PB * PN)        // 4096 tokens
#define QKV_COLS (3 * PE)      // 3072

// Does this compilation pass support tcgen05 (arch-specific sm_10xa target)?
#if defined(__CUDA_ARCH_FEAT_SM103_ALL) || defined(__CUDA_ARCH_FEAT_SM101_ALL) || defined(__CUDA_ARCH_FEAT_SM100_ALL)
#define HAS_TC 1
#else
#define HAS_TC 0
#endif

// Scratch (no cudaMalloc allowed)
__device__ float g_Q[PB * PH * PN * PD];   // [B,H,N,D]
__device__ float g_K[PB * PH * PN * PD];
__device__ float g_V[PB * PH * PN * PD];
__device__ float g_O[M_TOK * PE];          // [B,N,E] pre-projection

// ===========================================================================
// PTX helpers
// ===========================================================================
__device__ __forceinline__ uint32_t smem_u32(const void* p) {
    uint32_t a;
    asm("{ .reg .u64 t; cvta.to.shared.u64 t, %1; cvt.u32.u64 %0, t; }"
        : "=r"(a) : "l"(p));
    return a;
}

#if HAS_TC
__device__ __forceinline__ uint32_t elect_one() {
    uint32_t pred;
    asm volatile("{\n\t.reg .pred p;\n\telect.sync _|p, 0xFFFFFFFF;\n\t"
                 "selp.b32 %0, 1, 0, p;\n\t}" : "=r"(pred));
    return pred;
}
#define TC_ALLOC(sm, n)  asm volatile("tcgen05.alloc.cta_group::1.sync.aligned.shared::cta.b32 [%0], %1;" :: "r"((uint32_t)(sm)), "r"((uint32_t)(n)) : "memory")
#define TC_DEALLOC(t, n) asm volatile("tcgen05.dealloc.cta_group::1.sync.aligned.b32 %0, %1;" :: "r"(t), "r"((uint32_t)(n)))
#define TC_RELINQ()      asm volatile("tcgen05.relinquish_alloc_permit.cta_group::1.sync.aligned;")
#define TC_COMMIT(mb)    asm volatile("tcgen05.commit.cta_group::1.mbarrier::arrive::one.shared::cluster.b64 [%0];" :: "r"((uint32_t)(mb)) : "memory")
#define TC_FENCE_AFTER() asm volatile("tcgen05.fence::after_thread_sync;" ::: "memory")
#define TC_FENCE_BEFORE() asm volatile("tcgen05.fence::before_thread_sync;" ::: "memory")
#define TC_WAIT_LD()     asm volatile("tcgen05.wait::ld.sync.aligned;" ::: "memory")
#define MBAR_INIT(mb, c) asm volatile("mbarrier.init.shared.b64 [%0], %1;" :: "r"((uint32_t)(mb)), "r"((uint32_t)(c)) : "memory")
#define MBAR_INVAL(mb)   asm volatile("mbarrier.inval.shared.b64 [%0];" :: "r"((uint32_t)(mb)) : "memory")

#define MBAR_WAIT(mb, ph) do {                                             \
    uint32_t _m = (uint32_t)(mb); uint32_t _p = (uint32_t)(ph); uint32_t _d;\
    asm volatile("{\n\t.reg .pred p;\n\t"                                  \
        "mbarrier.try_wait.parity.acquire.cta.shared::cta.b64 p, [%1], %2;\n\t" \
        "selp.b32 %0, 1, 0, p;\n\t}" : "=r"(_d) : "r"(_m), "r"(_p) : "memory"); \
    if (!_d) {                                                             \
        asm volatile("{\n\t.reg .pred P1;\n\t"                             \
            "WL_%=:\n\t"                                                   \
            "mbarrier.try_wait.parity.acquire.cta.shared::cta.b64 P1, [%0], %1, 0x989680;\n\t" \
            "@P1 bra.uni WD_%=;\n\t"                                       \
            "bra.uni WL_%=;\n\t"                                           \
            "WD_%=:\n\t}" :: "r"(_m), "r"(_p) : "memory");                 \
    }                                                                      \
} while (0)

#define TC_LD32X32(r, ta)                                                  \
    asm volatile("tcgen05.ld.sync.aligned.32x32b.x32.b32 "                 \
        "{%0, %1, %2, %3, %4, %5, %6, %7, "                                \
        " %8, %9, %10, %11, %12, %13, %14, %15, "                          \
        " %16, %17, %18, %19, %20, %21, %22, %23, "                        \
        " %24, %25, %26, %27, %28, %29, %30, %31}, [%32];"                 \
        : "=r"((r)[0]),  "=r"((r)[1]),  "=r"((r)[2]),  "=r"((r)[3]),       \
          "=r"((r)[4]),  "=r"((r)[5]),  "=r"((r)[6]),  "=r"((r)[7]),       \
          "=r"((r)[8]),  "=r"((r)[9]),  "=r"((r)[10]), "=r"((r)[11]),      \
          "=r"((r)[12]), "=r"((r)[13]), "=r"((r)[14]), "=r"((r)[15]),      \
          "=r"((r)[16]), "=r"((r)[17]), "=r"((r)[18]), "=r"((r)[19]),      \
          "=r"((r)[20]), "=r"((r)[21]), "=r"((r)[22]), "=r"((r)[23]),      \
          "=r"((r)[24]), "=r"((r)[25]), "=r"((r)[26]), "=r"((r)[27]),      \
          "=r"((r)[28]), "=r"((r)[29]), "=r"((r)[30]), "=r"((r)[31])       \
        : "r"(ta))

// SW128 K-major smem descriptor: layout=2, version=1, SBO=64, LBO=1
__device__ __forceinline__ uint64_t make_desc(uint32_t base) {
    uint64_t d = (uint64_t)2 << 61 | (uint64_t)1 << 46 |
                 (uint64_t)64 << 32 | (uint64_t)1 << 16;
    return d | ((uint64_t)(base >> 4) & 0x3FFF);
}

__device__ __forceinline__ void mma_tf32_ss(uint32_t d, uint64_t ad, uint64_t bd,
                                            uint32_t idesc, uint32_t en) {
    asm volatile("{\n\t.reg .pred p;\n\tsetp.ne.u32 p, %5, 0;\n\t"
                 "tcgen05.mma.cta_group::1.kind::tf32 [%0], %1, %2, %3, "
                 "{%4, %4, %4, %4}, p;\n\t}"
                 :: "r"(d), "l"(ad), "l"(bd), "r"(idesc), "r"(0u), "r"(en)
                 : "memory");
}

__device__ __forceinline__ uint32_t f2tf32(float f) {
    uint32_t r;
    asm("cvt.rna.tf32.f32 %0, %1;" : "=r"(r) : "f"(f));
    return r;
}
#endif  // HAS_TC

// ===========================================================================
// GEMM-NT: C[M,Ncols] = A[M,K] * Bm[Ncols,K]^T (+bias).
// 128x128 tile per CTA, 256 threads, grid (Ncols/128, M/128).
// Device body: tcgen05 tf32 SS MMA if HAS_TC, else FFMA 8x8 microtile SGEMM.
// EPI 0: scatter into g_Q/g_K/g_V with bias. EPI 1: plain store + bias.
// ===========================================================================
// idesc: dtype f32(1), atype/btype tf32(2), N=128, M=128
#define IDESC_TF32 ((1u << 4) | (2u << 7) | (2u << 10) | ((128u / 8) << 17) | ((128u / 16) << 24))
#define GEMM_SMEM 69632

template <int EPI>
__global__ void __launch_bounds__(256, 2) __cluster_dims__(1, 1, 1)
gemm_any(const float* __restrict__ A, const float* __restrict__ Bm,
         const float* __restrict__ bias, float* __restrict__ C,
         int Ncols, int K)
{
    extern __shared__ char smem[];
    const int tid = threadIdx.x;
    const int m0 = blockIdx.y * 128;
    const int n0 = blockIdx.x * 128;

#if HAS_TC
    // ------------------------- tcgen05 tf32 path -------------------------
    const uint32_t smem_base = smem_u32(smem);
    const int wid = tid >> 5;
    const int lid = tid & 31;
    // 1024-aligned base for SW128 tiles (header lives below it)
    const uint32_t abase = (smem_base + 32 + 1023) & ~1023u;
    const uint32_t hdr_off = 0;              // tmem ptr at smem_base
    const uint32_t mbar0 = smem_base + 8;
    const uint32_t mbar1 = smem_base + 16;

    if (wid == 0) {
        TC_ALLOC(smem_base + hdr_off, 128);
        if (elect_one()) { MBAR_INIT(mbar0, 1); MBAR_INIT(mbar1, 1); }
    }
    __syncthreads();
    uint32_t tmem_base;
    asm volatile("ld.shared.b32 %0, [%1];" : "=r"(tmem_base) : "r"(smem_base + hdr_off));

    const int nchunks = K / 32;
    int phase[2] = {0, 0};

    for (int c = 0; c < nchunks; c++) {
        const int s = c & 1;
        if (c >= 2) {
            MBAR_WAIT(s ? mbar1 : mbar0, phase[s]);
            phase[s] ^= 1;
        }
        // Load A tile [128 x 32] and B tile [128 x 32] into stage s (SW128)
        char* stage = smem + (abase - smem_base) + s * 32768;
        const int kt = c * 32;
#pragma unroll
        for (int t = 0; t < 8; t++) {
            int idx = tid + t * 256;            // 0..2047 float4 slots
            int isB = idx >> 10;
            int r = (idx & 1023) >> 3;          // 0..127
            int q = idx & 7;                    // float4 within 128B row
            const float* src = (isB ? Bm + (size_t)(n0 + r) * K
                                    : A + (size_t)(m0 + r) * K) + kt + 4 * q;
            float4 v = *(const float4*)src;
            uint4 o;
            o.x = f2tf32(v.x); o.y = f2tf32(v.y);
            o.z = f2tf32(v.z); o.w = f2tf32(v.w);
            uint32_t bo = (uint32_t)(r * 128 + q * 16);
            uint32_t sw = bo ^ ((bo >> 3) & 0x70);
            *(uint4*)(stage + (isB ? 16384 : 0) + sw) = o;
        }
        __syncthreads();
        if (wid == 0 && elect_one()) {
            uint64_t ad = make_desc(abase + s * 32768);
            uint64_t bd = make_desc(abase + s * 32768 + 16384);
#pragma unroll
            for (int k4 = 0; k4 < 4; k4++)
                mma_tf32_ss(tmem_base, ad + k4 * 2, bd + k4 * 2, IDESC_TF32,
                            (c > 0 || k4 > 0) ? 1u : 0u);
            TC_COMMIT(s ? mbar1 : mbar0);
        }
    }
    // Drain both stages
    MBAR_WAIT(mbar0, phase[0]);
    MBAR_WAIT(mbar1, phase[1]);
    TC_FENCE_AFTER();

    // Epilogue: TMEM -> smem, then stores (warps 0-3 read the 128 TMEM lanes)
    float* eps = (float*)(smem + (abase - smem_base));
    const int ESTRIDE = 132;
    if (wid < 4) {
#pragma unroll
        for (int base = 0; base < 128; base += 32) {
            uint32_t r[32];
            TC_LD32X32(r, tmem_base + base);
            TC_WAIT_LD();
#pragma unroll
            for (int cc = 0; cc < 32; cc++)
                eps[(wid * 32 + lid) * ESTRIDE + base + cc] = __uint_as_float(r[cc]);
        }
        TC_FENCE_BEFORE();
    }
    __syncthreads();

    if (EPI == 1) {
        for (int idx = tid; idx < 128 * 32; idx += 256) {
            int row = idx >> 5, q = idx & 31;
            float4 v = *(const float4*)&eps[row * ESTRIDE + 4 * q];
            int colg = n0 + 4 * q;
            v.x += bias[colg + 0]; v.y += bias[colg + 1];
            v.z += bias[colg + 2]; v.w += bias[colg + 3];
            *(float4*)(C + (size_t)(m0 + row) * Ncols + colg) = v;
        }
    } else {
        for (int idx = tid; idx < 128 * 128; idx += 256) {
            int row = idx >> 7, col = idx & 127;
            int colg = n0 + col;
            float v = eps[row * ESTRIDE + col] + bias[colg];
            int which = colg % 3;
            int rest = colg / 3;            // h*64 + d
            int h = rest >> 6;
            int d = rest & 63;
            int tok = m0 + row;
            int bb = tok >> 11;
            int n = tok & 2047;
            size_t dst = (((size_t)(bb * PH + h)) * PN + n) * PD + d;
            float* out = (which == 0) ? g_Q : (which == 1) ? g_K : g_V;
            out[dst] = v;
        }
    }

    __syncthreads();
    if (wid == 0) {
        if (elect_one()) { MBAR_INVAL(mbar0); MBAR_INVAL(mbar1); }
        TC_RELINQ();
        TC_DEALLOC(tmem_base, 128);
    }
#else
    // ------------------------- FFMA fallback path -------------------------
    float (*As)[132] = reinterpret_cast<float(*)[132]>(smem);
    float (*Bs)[132] = reinterpret_cast<float(*)[132]>(smem + 16 * 132 * sizeof(float));

    const int tx = tid & 15;
    const int ty = tid >> 4;

    float acc[8][8];
#pragma unroll
    for (int i = 0; i < 8; i++)
#pragma unroll
        for (int j = 0; j < 8; j++) acc[i][j] = 0.f;

    for (int kt = 0; kt < K; kt += 16) {
#pragma unroll
        for (int e = 0; e < 2; e++) {
            int idx = tid + e * 256;      // 0..511 float4 slots
            int row = idx >> 2;           // 0..127
            int kq  = (idx & 3) << 2;     // 0,4,8,12
            float4 a = *(const float4*)(A + (size_t)(m0 + row) * K + kt + kq);
            As[kq + 0][row] = a.x; As[kq + 1][row] = a.y;
            As[kq + 2][row] = a.z; As[kq + 3][row] = a.w;
            float4 b = *(const float4*)(Bm + (size_t)(n0 + row) * K + kt + kq);
            Bs[kq + 0][row] = b.x; Bs[kq + 1][row] = b.y;
            Bs[kq + 2][row] = b.z; Bs[kq + 3][row] = b.w;
        }
        __syncthreads();
#pragma unroll
        for (int kk = 0; kk < 16; kk++) {
            float a[8], b[8];
            *(float4*)(a + 0) = *(const float4*)&As[kk][4 * ty];
            *(float4*)(a + 4) = *(const float4*)&As[kk][64 + 4 * ty];
            *(float4*)(b + 0) = *(const float4*)&Bs[kk][4 * tx];
            *(float4*)(b + 4) = *(const float4*)&Bs[kk][64 + 4 * tx];
#pragma unroll
            for (int i = 0; i < 8; i++)
#pragma unroll
                for (int j = 0; j < 8; j++) acc[i][j] += a[i] * b[j];
        }
        __syncthreads();
    }

#pragma unroll
    for (int bi = 0; bi < 2; bi++) {
#pragma unroll
        for (int i = 0; i < 4; i++) {
            int row = m0 + bi * 64 + 4 * ty + i;  // token index
#pragma unroll
            for (int bj = 0; bj < 2; bj++) {
                if (EPI == 1) {
                    int col = n0 + bj * 64 + 4 * tx;
                    float4 v;
                    v.x = acc[bi * 4 + i][bj * 4 + 0] + bias[col + 0];
                    v.y = acc[bi * 4 + i][bj * 4 + 1] + bias[col + 1];
                    v.z = acc[bi * 4 + i][bj * 4 + 2] + bias[col + 2];
                    v.w = acc[bi * 4 + i][bj * 4 + 3] + bias[col + 3];
                    *(float4*)(C + (size_t)row * Ncols + col) = v;
                } else {
#pragma unroll
                    for (int j = 0; j < 4; j++) {
                        int col = n0 + bj * 64 + 4 * tx + j;
                        float v = acc[bi * 4 + i][bj * 4 + j] + bias[col];
                        int which = col % 3;
                        int rest  = col / 3;          // h*64 + d
                        int h = rest >> 6;
                        int d = rest & 63;
                        int bb = row >> 11;
                        int n  = row & 2047;
                        size_t dst = (((size_t)(bb * PH + h)) * PN + n) * PD + d;
                        float* out = (which == 0) ? g_Q : (which == 1) ? g_K : g_V;
                        out[dst] = v;
                    }
                }
            }
        }
    }
#endif
}

// ---------------------------------------------------------------------------
// Flash attention, fp32. Br=Bc=64, 256 threads (16x16), online softmax.
// smem: Qs[64][64] | KP[64][65] (K tile, later reused for P) | Vs[64][64]
// ---------------------------------------------------------------------------
__global__ __launch_bounds__(256)
void flash_attn(const float* __restrict__ Qg, const float* __restrict__ Kg,
                const float* __restrict__ Vg, float* __restrict__ Og)
{
    extern __shared__ float sm[];
    float* Qs = sm;                 // 4096 floats
    float* KP = sm + 64 * 64;       // 4160 floats (stride 65)
    float* Vs = KP + 64 * 65;       // 4096 floats

    const int tid = threadIdx.x;
    const int tx = tid & 15;
    const int ty = tid >> 4;
    const int bh = blockIdx.y;          // b*H + h
    const int n0 = blockIdx.x * 64;     // query tile start
    const size_t base = (size_t)bh * PN * PD;
    const float scale = 0.125f;         // 1/sqrt(64)

    for (int idx = tid; idx < 64 * 64; idx += 256) {
        int r = idx >> 6, d = idx & 63;
        Qs[r * 64 + d] = Qg[base + (size_t)(n0 + r) * PD + d];
    }

    float o[4][4];
    float m_i[4], l_i[4];
#pragma unroll
    for (int i = 0; i < 4; i++) {
        m_i[i] = -INFINITY; l_i[i] = 0.f;
#pragma unroll
        for (int j = 0; j < 4; j++) o[i][j] = 0.f;
    }
    __syncthreads();

    for (int kt = 0; kt < PN / 64; kt++) {
        int k0 = kt * 64;
        for (int idx = tid; idx < 64 * 64; idx += 256) {
            int r = idx >> 6, d = idx & 63;
            KP[r * 65 + d] = Kg[base + (size_t)(k0 + r) * PD + d];
            Vs[r * 64 + d] = Vg[base + (size_t)(k0 + r) * PD + d];
        }
        __syncthreads();

        float s[4][4];
#pragma unroll
        for (int i = 0; i < 4; i++)
#pragma unroll
            for (int j = 0; j < 4; j++) s[i][j] = 0.f;

        for (int k = 0; k < 64; k += 4) {
            float q[4][4];
#pragma unroll
            for (int i = 0; i < 4; i++) {
                float4 t = *(const float4*)&Qs[(4 * ty + i) * 64 + k];
                q[i][0] = t.x; q[i][1] = t.y; q[i][2] = t.z; q[i][3] = t.w;
            }
#pragma unroll
            for (int kk = 0; kk < 4; kk++) {
                float kv[4];
#pragma unroll
                for (int j = 0; j < 4; j++)
                    kv[j] = KP[(4 * tx + j) * 65 + k + kk];
#pragma unroll
                for (int i = 0; i < 4; i++)
#pragma unroll
                    for (int j = 0; j < 4; j++)
                        s[i][j] += q[i][kk] * kv[j];
            }
        }

        float mnew[4], alpha[4];
#pragma unroll
        for (int i = 0; i < 4; i++) {
            float mt = s[i][0];
#pragma unroll
            for (int j = 1; j < 4; j++) mt = fmaxf(mt, s[i][j]);
            mt *= scale;
#pragma unroll
            for (int off = 8; off >= 1; off >>= 1)
                mt = fmaxf(mt, __shfl_xor_sync(0xffffffffu, mt, off));
            mnew[i] = fmaxf(m_i[i], mt);
            alpha[i] = __expf(m_i[i] - mnew[i]);
            m_i[i] = mnew[i];
        }
        float p[4][4];
#pragma unroll
        for (int i = 0; i < 4; i++) {
            float lt = 0.f;
#pragma unroll
            for (int j = 0; j < 4; j++) {
                p[i][j] = __expf(s[i][j] * scale - mnew[i]);
                lt += p[i][j];
            }
#pragma unroll
            for (int off = 8; off >= 1; off >>= 1)
                lt += __shfl_xor_sync(0xffffffffu, lt, off);
            l_i[i] = l_i[i] * alpha[i] + lt;
#pragma unroll
            for (int j = 0; j < 4; j++) o[i][j] *= alpha[i];
        }

        __syncthreads();
#pragma unroll
        for (int i = 0; i < 4; i++)
#pragma unroll
            for (int j = 0; j < 4; j++)
                KP[(4 * ty + i) * 65 + 4 * tx + j] = p[i][j];
        __syncthreads();

        for (int jj = 0; jj < 64; jj++) {
            float pv[4];
#pragma unroll
            for (int i = 0; i < 4; i++) pv[i] = KP[(4 * ty + i) * 65 + jj];
            float4 vv = *(const float4*)&Vs[jj * 64 + 4 * tx];
#pragma unroll
            for (int i = 0; i < 4; i++) {
                o[i][0] += pv[i] * vv.x;
                o[i][1] += pv[i] * vv.y;
                o[i][2] += pv[i] * vv.z;
                o[i][3] += pv[i] * vv.w;
            }
        }
        __syncthreads();
    }

    int b = bh / PH, h = bh % PH;
#pragma unroll
    for (int i = 0; i < 4; i++) {
        float inv_l = 1.f / l_i[i];
        int n = n0 + 4 * ty + i;
        float4 v;
        v.x = o[i][0] * inv_l; v.y = o[i][1] * inv_l;
        v.z = o[i][2] * inv_l; v.w = o[i][3] * inv_l;
        *(float4*)&g_O[((size_t)b * PN + n) * PE + h * 64 + 4 * tx] = v;
    }
    (void)Og;
}

// ---------------------------------------------------------------------------
extern "C" void kernel_launch(void* const* d_in, const int* in_sizes, int n_in,
                              void* d_out, int out_size)
{
    const float* x      = (const float*)d_in[0];
    const float* w_qkv  = (const float*)d_in[1];
    const float* b_qkv  = (const float*)d_in[2];
    const float* w_proj = (const float*)d_in[3];
    const float* b_proj = (const float*)d_in[4];
    float* out = (float*)d_out;

    const int fa_smem = (64 * 64 + 64 * 65 + 64 * 64) * sizeof(float); // 49408
    cudaFuncSetAttribute(gemm_any<0>,
                         cudaFuncAttributeMaxDynamicSharedMemorySize, GEMM_SMEM);
    cudaFuncSetAttribute(gemm_any<1>,
                         cudaFuncAttributeMaxDynamicSharedMemorySize, GEMM_SMEM);
    cudaFuncSetAttribute(flash_attn,
                         cudaFuncAttributeMaxDynamicSharedMemorySize, fa_smem);

    // 1) QKV projection + scatter
    {
        dim3 grid(QKV_COLS / 128, M_TOK / 128);
        gemm_any<0><<<grid, 256, GEMM_SMEM>>>(x, w_qkv, b_qkv, nullptr,
                                              QKV_COLS, PE);
    }

    // 2) Flash attention (fp32)
    {
        dim3 grid(PN / 64, PB * PH);
        float *Qp, *Kp, *Vp, *Op;
        cudaGetSymbolAddress((void**)&Qp, g_Q);
        cudaGetSymbolAddress((void**)&Kp, g_K);
        cudaGetSymbolAddress((void**)&Vp, g_V);
        cudaGetSymbolAddress((void**)&Op, g_O);
        flash_attn<<<grid, 256, fa_smem>>>(Qp, Kp, Vp, Op);
    }

    // 3) Output projection
    {
        float* Op;
        cudaGetSymbolAddress((void**)&Op, g_O);
        dim3 grid(PE / 128, M_TOK / 128);
        gemm_any<1><<<grid, 256, GEMM_SMEM>>>(Op, w_proj, b_proj, out,
                                              PE, PE);
    }
}

// round 11
// speedup vs baseline: 3.7373x; 2.5622x over previous
#include <cuda_runtime.h>
#include <math.h>
#include <stdint.h>

// Problem constants
#define PB 2
#define PN 2048
#define PE 1024
#define PH 16
#define PD 64
#define M_TOK (PB * PN)        // 4096 tokens
#define QKV_COLS (3 * PE)      // 3072

// Does this compilation pass support tcgen05 (arch-specific sm_10xa target)?
#if defined(__CUDA_ARCH_FEAT_SM103_ALL) || defined(__CUDA_ARCH_FEAT_SM101_ALL) || defined(__CUDA_ARCH_FEAT_SM100_ALL)
#define HAS_TC 1
#else
#define HAS_TC 0
#endif

// Scratch (no cudaMalloc allowed)
__device__ float g_Q[PB * PH * PN * PD];   // [B,H,N,D]
__device__ float g_K[PB * PH * PN * PD];   // [B,H,N,D]
__device__ float g_V[PB * PH * PN * PD];   // [B,H,D,N]  (TRANSPOSED for MMA2 B operand)
__device__ float g_O[M_TOK * PE];          // [B,N,E] pre-projection

// ===========================================================================
// PTX helpers
// ===========================================================================
__device__ __forceinline__ uint32_t smem_u32(const void* p) {
    uint32_t a;
    asm("{ .reg .u64 t; cvta.to.shared.u64 t, %1; cvt.u32.u64 %0, t; }"
        : "=r"(a) : "l"(p));
    return a;
}

#if HAS_TC
__device__ __forceinline__ uint32_t elect_one() {
    uint32_t pred;
    asm volatile("{\n\t.reg .pred p;\n\telect.sync _|p, 0xFFFFFFFF;\n\t"
                 "selp.b32 %0, 1, 0, p;\n\t}" : "=r"(pred));
    return pred;
}
#define TC_ALLOC(sm, n)  asm volatile("tcgen05.alloc.cta_group::1.sync.aligned.shared::cta.b32 [%0], %1;" :: "r"((uint32_t)(sm)), "r"((uint32_t)(n)) : "memory")
#define TC_DEALLOC(t, n) asm volatile("tcgen05.dealloc.cta_group::1.sync.aligned.b32 %0, %1;" :: "r"(t), "r"((uint32_t)(n)))
#define TC_RELINQ()      asm volatile("tcgen05.relinquish_alloc_permit.cta_group::1.sync.aligned;")
#define TC_COMMIT(mb)    asm volatile("tcgen05.commit.cta_group::1.mbarrier::arrive::one.shared::cluster.b64 [%0];" :: "r"((uint32_t)(mb)) : "memory")
#define TC_FENCE_AFTER() asm volatile("tcgen05.fence::after_thread_sync;" ::: "memory")
#define TC_FENCE_BEFORE() asm volatile("tcgen05.fence::before_thread_sync;" ::: "memory")
#define TC_WAIT_LD()     asm volatile("tcgen05.wait::ld.sync.aligned;" ::: "memory")
#define MBAR_INIT(mb, c) asm volatile("mbarrier.init.shared.b64 [%0], %1;" :: "r"((uint32_t)(mb)), "r"((uint32_t)(c)) : "memory")
#define MBAR_INVAL(mb)   asm volatile("mbarrier.inval.shared.b64 [%0];" :: "r"((uint32_t)(mb)) : "memory")

#define MBAR_WAIT(mb, ph) do {                                             \
    uint32_t _m = (uint32_t)(mb); uint32_t _p = (uint32_t)(ph); uint32_t _d;\
    asm volatile("{\n\t.reg .pred p;\n\t"                                  \
        "mbarrier.try_wait.parity.acquire.cta.shared::cta.b64 p, [%1], %2;\n\t" \
        "selp.b32 %0, 1, 0, p;\n\t}" : "=r"(_d) : "r"(_m), "r"(_p) : "memory"); \
    if (!_d) {                                                             \
        asm volatile("{\n\t.reg .pred P1;\n\t"                             \
            "WL_%=:\n\t"                                                   \
            "mbarrier.try_wait.parity.acquire.cta.shared::cta.b64 P1, [%0], %1, 0x989680;\n\t" \
            "@P1 bra.uni WD_%=;\n\t"                                       \
            "bra.uni WL_%=;\n\t"                                           \
            "WD_%=:\n\t}" :: "r"(_m), "r"(_p) : "memory");                 \
    }                                                                      \
} while (0)

#define TC_LD32X32(r, ta)                                                  \
    asm volatile("tcgen05.ld.sync.aligned.32x32b.x32.b32 "                 \
        "{%0, %1, %2, %3, %4, %5, %6, %7, "                                \
        " %8, %9, %10, %11, %12, %13, %14, %15, "                          \
        " %16, %17, %18, %19, %20, %21, %22, %23, "                        \
        " %24, %25, %26, %27, %28, %29, %30, %31}, [%32];"                 \
        : "=r"((r)[0]),  "=r"((r)[1]),  "=r"((r)[2]),  "=r"((r)[3]),       \
          "=r"((r)[4]),  "=r"((r)[5]),  "=r"((r)[6]),  "=r"((r)[7]),       \
          "=r"((r)[8]),  "=r"((r)[9]),  "=r"((r)[10]), "=r"((r)[11]),      \
          "=r"((r)[12]), "=r"((r)[13]), "=r"((r)[14]), "=r"((r)[15]),      \
          "=r"((r)[16]), "=r"((r)[17]), "=r"((r)[18]), "=r"((r)[19]),      \
          "=r"((r)[20]), "=r"((r)[21]), "=r"((r)[22]), "=r"((r)[23]),      \
          "=r"((r)[24]), "=r"((r)[25]), "=r"((r)[26]), "=r"((r)[27]),      \
          "=r"((r)[28]), "=r"((r)[29]), "=r"((r)[30]), "=r"((r)[31])       \
        : "r"(ta))

// SW128 K-major smem descriptor: layout=2, version=1, SBO=64, LBO=1
__device__ __forceinline__ uint64_t make_desc(uint32_t base) {
    uint64_t d = (uint64_t)2 << 61 | (uint64_t)1 << 46 |
                 (uint64_t)64 << 32 | (uint64_t)1 << 16;
    return d | ((uint64_t)(base >> 4) & 0x3FFF);
}

__device__ __forceinline__ void mma_tf32_ss(uint32_t d, uint64_t ad, uint64_t bd,
                                            uint32_t idesc, uint32_t en) {
    asm volatile("{\n\t.reg .pred p;\n\tsetp.ne.u32 p, %5, 0;\n\t"
                 "tcgen05.mma.cta_group::1.kind::tf32 [%0], %1, %2, %3, "
                 "{%4, %4, %4, %4}, p;\n\t}"
                 :: "r"(d), "l"(ad), "l"(bd), "r"(idesc), "r"(0u), "r"(en)
                 : "memory");
}

__device__ __forceinline__ uint32_t f2tf32(float f) {
    uint32_t r;
    asm("cvt.rna.tf32.f32 %0, %1;" : "=r"(r) : "f"(f));
    return r;
}
#endif  // HAS_TC

// ===========================================================================
// GEMM-NT: C[M,Ncols] = A[M,K] * Bm[Ncols,K]^T (+bias).
// 128x128 tile per CTA, 256 threads, grid (Ncols/128, M/128).
// EPI 0: scatter into g_Q/g_K (N,D) and g_V (D,N transposed) with bias.
// EPI 1: plain store + bias.
// ===========================================================================
#define IDESC_TF32 ((1u << 4) | (2u << 7) | (2u << 10) | ((128u / 8) << 17) | ((128u / 16) << 24))
#define GEMM_SMEM 69632

template <int EPI>
__global__ void __launch_bounds__(256, 2) __cluster_dims__(1, 1, 1)
gemm_any(const float* __restrict__ A, const float* __restrict__ Bm,
         const float* __restrict__ bias, float* __restrict__ C,
         int Ncols, int K)
{
    extern __shared__ char smem[];
    const int tid = threadIdx.x;
    const int m0 = blockIdx.y * 128;
    const int n0 = blockIdx.x * 128;

#if HAS_TC
    const uint32_t smem_base = smem_u32(smem);
    const int wid = tid >> 5;
    const int lid = tid & 31;
    const uint32_t abase = (smem_base + 32 + 1023) & ~1023u;
    const uint32_t mbar0 = smem_base + 8;
    const uint32_t mbar1 = smem_base + 16;

    if (wid == 0) {
        TC_ALLOC(smem_base, 128);
        if (elect_one()) { MBAR_INIT(mbar0, 1); MBAR_INIT(mbar1, 1); }
    }
    __syncthreads();
    uint32_t tmem_base;
    asm volatile("ld.shared.b32 %0, [%1];" : "=r"(tmem_base) : "r"(smem_base));

    const int nchunks = K / 32;
    int phase[2] = {0, 0};

    for (int c = 0; c < nchunks; c++) {
        const int s = c & 1;
        if (c >= 2) {
            MBAR_WAIT(s ? mbar1 : mbar0, phase[s]);
            phase[s] ^= 1;
        }
        char* stage = smem + (abase - smem_base) + s * 32768;
        const int kt = c * 32;
#pragma unroll
        for (int t = 0; t < 8; t++) {
            int idx = tid + t * 256;
            int isB = idx >> 10;
            int r = (idx & 1023) >> 3;
            int q = idx & 7;
            const float* src = (isB ? Bm + (size_t)(n0 + r) * K
                                    : A + (size_t)(m0 + r) * K) + kt + 4 * q;
            float4 v = *(const float4*)src;
            uint4 o;
            o.x = f2tf32(v.x); o.y = f2tf32(v.y);
            o.z = f2tf32(v.z); o.w = f2tf32(v.w);
            uint32_t bo = (uint32_t)(r * 128 + q * 16);
            uint32_t sw = bo ^ ((bo >> 3) & 0x70);
            *(uint4*)(stage + (isB ? 16384 : 0) + sw) = o;
        }
        __syncthreads();
        if (wid == 0 && elect_one()) {
            uint64_t ad = make_desc(abase + s * 32768);
            uint64_t bd = make_desc(abase + s * 32768 + 16384);
#pragma unroll
            for (int k4 = 0; k4 < 4; k4++)
                mma_tf32_ss(tmem_base, ad + k4 * 2, bd + k4 * 2, IDESC_TF32,
                            (c > 0 || k4 > 0) ? 1u : 0u);
            TC_COMMIT(s ? mbar1 : mbar0);
        }
    }
    MBAR_WAIT(mbar0, phase[0]);
    MBAR_WAIT(mbar1, phase[1]);
    TC_FENCE_AFTER();

    float* eps = (float*)(smem + (abase - smem_base));
    const int ESTRIDE = 132;
    if (wid < 4) {
#pragma unroll
        for (int base = 0; base < 128; base += 32) {
            uint32_t r[32];
            TC_LD32X32(r, tmem_base + base);
            TC_WAIT_LD();
#pragma unroll
            for (int cc = 0; cc < 32; cc++)
                eps[(wid * 32 + lid) * ESTRIDE + base + cc] = __uint_as_float(r[cc]);
        }
        TC_FENCE_BEFORE();
    }
    __syncthreads();

    if (EPI == 1) {
        for (int idx = tid; idx < 128 * 32; idx += 256) {
            int row = idx >> 5, q = idx & 31;
            float4 v = *(const float4*)&eps[row * ESTRIDE + 4 * q];
            int colg = n0 + 4 * q;
            v.x += bias[colg + 0]; v.y += bias[colg + 1];
            v.z += bias[colg + 2]; v.w += bias[colg + 3];
            *(float4*)(C + (size_t)(m0 + row) * Ncols + colg) = v;
        }
    } else {
        for (int idx = tid; idx < 128 * 128; idx += 256) {
            int row = idx >> 7, col = idx & 127;
            int colg = n0 + col;
            float v = eps[row * ESTRIDE + col] + bias[colg];
            int which = colg % 3;
            int rest = colg / 3;            // h*64 + d
            int h = rest >> 6;
            int d = rest & 63;
            int tok = m0 + row;
            int bb = tok >> 11;
            int n = tok & 2047;
            size_t dst;
            float* out;
            if (which == 0)      { out = g_Q; dst = (((size_t)(bb * PH + h)) * PN + n) * PD + d; }
            else if (which == 1) { out = g_K; dst = (((size_t)(bb * PH + h)) * PN + n) * PD + d; }
            else                 { out = g_V; dst = (((size_t)(bb * PH + h)) * PD + d) * PN + n; }
            out[dst] = v;
        }
    }

    __syncthreads();
    if (wid == 0) {
        if (elect_one()) { MBAR_INVAL(mbar0); MBAR_INVAL(mbar1); }
        TC_RELINQ();
        TC_DEALLOC(tmem_base, 128);
    }
#else
    // ------------------------- FFMA fallback path -------------------------
    float (*As)[132] = reinterpret_cast<float(*)[132]>(smem);
    float (*Bs)[132] = reinterpret_cast<float(*)[132]>(smem + 16 * 132 * sizeof(float));

    const int tx = tid & 15;
    const int ty = tid >> 4;

    float acc[8][8];
#pragma unroll
    for (int i = 0; i < 8; i++)
#pragma unroll
        for (int j = 0; j < 8; j++) acc[i][j] = 0.f;

    for (int kt = 0; kt < K; kt += 16) {
#pragma unroll
        for (int e = 0; e < 2; e++) {
            int idx = tid + e * 256;
            int row = idx >> 2;
            int kq  = (idx & 3) << 2;
            float4 a = *(const float4*)(A + (size_t)(m0 + row) * K + kt + kq);
            As[kq + 0][row] = a.x; As[kq + 1][row] = a.y;
            As[kq + 2][row] = a.z; As[kq + 3][row] = a.w;
            float4 b = *(const float4*)(Bm + (size_t)(n0 + row) * K + kt + kq);
            Bs[kq + 0][row] = b.x; Bs[kq + 1][row] = b.y;
            Bs[kq + 2][row] = b.z; Bs[kq + 3][row] = b.w;
        }
        __syncthreads();
#pragma unroll
        for (int kk = 0; kk < 16; kk++) {
            float a[8], b[8];
            *(float4*)(a + 0) = *(const float4*)&As[kk][4 * ty];
            *(float4*)(a + 4) = *(const float4*)&As[kk][64 + 4 * ty];
            *(float4*)(b + 0) = *(const float4*)&Bs[kk][4 * tx];
            *(float4*)(b + 4) = *(const float4*)&Bs[kk][64 + 4 * tx];
#pragma unroll
            for (int i = 0; i < 8; i++)
#pragma unroll
                for (int j = 0; j < 8; j++) acc[i][j] += a[i] * b[j];
        }
        __syncthreads();
    }

#pragma unroll
    for (int bi = 0; bi < 2; bi++) {
#pragma unroll
        for (int i = 0; i < 4; i++) {
            int row = m0 + bi * 64 + 4 * ty + i;
#pragma unroll
            for (int bj = 0; bj < 2; bj++) {
                if (EPI == 1) {
                    int col = n0 + bj * 64 + 4 * tx;
                    float4 v;
                    v.x = acc[bi * 4 + i][bj * 4 + 0] + bias[col + 0];
                    v.y = acc[bi * 4 + i][bj * 4 + 1] + bias[col + 1];
                    v.z = acc[bi * 4 + i][bj * 4 + 2] + bias[col + 2];
                    v.w = acc[bi * 4 + i][bj * 4 + 3] + bias[col + 3];
                    *(float4*)(C + (size_t)row * Ncols + col) = v;
                } else {
#pragma unroll
                    for (int j = 0; j < 4; j++) {
                        int col = n0 + bj * 64 + 4 * tx + j;
                        float v = acc[bi * 4 + i][bj * 4 + j] + bias[col];
                        int which = col % 3;
                        int rest  = col / 3;
                        int h = rest >> 6;
                        int d = rest & 63;
                        int bb = row >> 11;
                        int n  = row & 2047;
                        size_t dst;
                        float* out;
                        if (which == 0)      { out = g_Q; dst = (((size_t)(bb * PH + h)) * PN + n) * PD + d; }
                        else if (which == 1) { out = g_K; dst = (((size_t)(bb * PH + h)) * PN + n) * PD + d; }
                        else                 { out = g_V; dst = (((size_t)(bb * PH + h)) * PD + d) * PN + n; }
                        out[dst] = v;
                    }
                }
            }
        }
    }
#endif
}

// ===========================================================================
// Flash attention. TC path: tcgen05 tf32, 128q x 128k tiles, 256 threads.
//   TMEM: S at cols 0..127, O at cols 128..191 (alloc 256).
//   smem tiles (1024-aligned): Qs 2x[128][32] | Ks/P01 | P23 | Vt 4x[64][32]
// Fallback: FFMA, two 64-row passes. Both read g_V TRANSPOSED [B,H,D,N].
// Grid (PN/128, PB*PH), 256 threads, dynamic smem FA_SMEM.
// ===========================================================================
#define FA_SMEM 136704
#define IDESC_S ((1u << 4) | (2u << 7) | (2u << 10) | ((128u / 8) << 17) | ((128u / 16) << 24))
#define IDESC_O ((1u << 4) | (2u << 7) | (2u << 10) | ((64u / 8) << 17) | ((128u / 16) << 24))

__global__ void __launch_bounds__(256, 1)
flash_attn(const float* __restrict__ Qg, const float* __restrict__ Kg,
           const float* __restrict__ Vtg, float* __restrict__ Og)
{
    extern __shared__ char smem[];
    const int tid = threadIdx.x;
    const int bh = blockIdx.y;
    const size_t baseQK = (size_t)bh * PN * PD;
    const size_t baseVt = (size_t)bh * PD * PN;
    const float scale = 0.125f;

#if HAS_TC
    const uint32_t smem_base = smem_u32(smem);
    const int wid = tid >> 5;
    const int lid = tid & 31;
    const int row = (wid & 3) * 32 + lid;   // query row within tile (= TMEM lane)
    const int colhalf = wid >> 2;           // 0: cols 0-63, 1: cols 64-127
    const int n0 = blockIdx.x * 128;

    const uint32_t mbarS = smem_base + 8;
    const uint32_t mbarO = smem_base + 16;
    float* rmax2 = (float*)(smem + 64);         // [2][128]
    float* rsum2 = (float*)(smem + 64 + 1024);  // [2][128]
    const uint32_t abase = (smem_base + 4096 + 1023) & ~1023u;
    char* atl = smem + (abase - smem_base);
    // Qs: atl+0 (2x16384) | Ks/P01: atl+32768 | P23: atl+65536 | Vt: atl+98304 (4x8192)

    if (wid == 0) {
        TC_ALLOC(smem_base, 256);
        if (elect_one()) { MBAR_INIT(mbarS, 1); MBAR_INIT(mbarO, 1); }
    }
    __syncthreads();
    uint32_t tmem_base;
    asm volatile("ld.shared.b32 %0, [%1];" : "=r"(tmem_base) : "r"(smem_base));

    // Load Q tile once: [128 rows][64 d] -> 2 SW128 chunks of [128][32]
#pragma unroll
    for (int t = 0; t < 8; t++) {
        int idx = tid + t * 256;            // float4 slots (16 per row)
        int r = idx >> 4;
        int q = idx & 15;
        float4 v = *(const float4*)(Qg + baseQK + (size_t)(n0 + r) * PD + 4 * q);
        uint4 o;
        o.x = f2tf32(v.x); o.y = f2tf32(v.y);
        o.z = f2tf32(v.z); o.w = f2tf32(v.w);
        uint32_t bo = (uint32_t)(r * 128 + (q & 7) * 16);
        uint32_t sw = bo ^ ((bo >> 3) & 0x70);
        *(uint4*)(atl + (q >> 3) * 16384 + sw) = o;
    }

    float acc[32];
#pragma unroll
    for (int k = 0; k < 32; k++) acc[k] = 0.f;
    float m_run = -INFINITY, l_run = 0.f;
    int phS = 0, phO = 0;

    for (int kt = 0; kt < PN / 128; kt++) {
        const int k0 = kt * 128;
        // ---- load K tile [128 keys][64 d] -> 2 chunks of [128][32] ----
#pragma unroll
        for (int t = 0; t < 8; t++) {
            int idx = tid + t * 256;
            int r = idx >> 4;           // 0..127 key
            int q = idx & 15;           // 16 float4 per row
            float4 v = *(const float4*)(Kg + baseQK + (size_t)(k0 + r) * PD + 4 * q);
            uint4 o;
            o.x = f2tf32(v.x); o.y = f2tf32(v.y);
            o.z = f2tf32(v.z); o.w = f2tf32(v.w);
            uint32_t bo = (uint32_t)(r * 128 + (q & 7) * 16);
            uint32_t sw = bo ^ ((bo >> 3) & 0x70);
            *(uint4*)(atl + 32768 + (q >> 3) * 16384 + sw) = o;
        }
        // ---- load Vt tile [64 d][128 keys] -> 4 chunks of [64][32] ----
        // FIX (round 10): Vt rows are 32 float4 wide (128 keys), 64 rows.
#pragma unroll
        for (int t = 0; t < 8; t++) {
            int idx = tid + t * 256;    // 0..2047
            int d = idx >> 5;           // 0..63
            int qk = idx & 31;          // float4 within row (32 per row)
            float4 v = *(const float4*)(Vtg + baseVt + (size_t)d * PN + k0 + 4 * qk);
            uint4 o;
            o.x = f2tf32(v.x); o.y = f2tf32(v.y);
            o.z = f2tf32(v.z); o.w = f2tf32(v.w);
            uint32_t bo = (uint32_t)(d * 128 + (qk & 7) * 16);
            uint32_t sw = bo ^ ((bo >> 3) & 0x70);
            *(uint4*)(atl + 98304 + (qk >> 3) * 8192 + sw) = o;
        }
        __syncthreads();

        // ---- MMA1: S = Q K^T ----
        if (wid == 0 && elect_one()) {
            TC_FENCE_AFTER();
#pragma unroll
            for (int c = 0; c < 2; c++) {
                uint64_t qd = make_desc(abase + c * 16384);
                uint64_t kd = make_desc(abase + 32768 + c * 16384);
#pragma unroll
                for (int k4 = 0; k4 < 4; k4++)
                    mma_tf32_ss(tmem_base, qd + k4 * 2, kd + k4 * 2, IDESC_S,
                                (c > 0 || k4 > 0) ? 1u : 0u);
            }
            TC_COMMIT(mbarS);
        }
        MBAR_WAIT(mbarS, phS); phS ^= 1;
        TC_FENCE_AFTER();

        // ---- softmax (thread owns half of S row `row`) ----
        uint32_t sr[64];
        TC_LD32X32(sr, tmem_base + 64 * colhalf);
        TC_LD32X32(sr + 32, tmem_base + 64 * colhalf + 32);
        TC_WAIT_LD();

        float mloc = -INFINITY;
#pragma unroll
        for (int j = 0; j < 64; j++) mloc = fmaxf(mloc, __uint_as_float(sr[j]));
        mloc *= scale;
        rmax2[colhalf * 128 + row] = mloc;
        __syncthreads();
        float mnew = fmaxf(m_run, fmaxf(rmax2[row], rmax2[128 + row]));
        float alpha = __expf(m_run - mnew);
        m_run = mnew;

        float lsum = 0.f;
#pragma unroll
        for (int j = 0; j < 64; j++) {
            float p = __expf(__uint_as_float(sr[j]) * scale - mnew);
            lsum += p;
            sr[j] = f2tf32(p);
        }
        rsum2[colhalf * 128 + row] = lsum;
#pragma unroll
        for (int k = 0; k < 32; k++) acc[k] *= alpha;

        // ---- store P (tf32) into chunks: keys 64*colhalf..+63 ----
#pragma unroll
        for (int jq = 0; jq < 16; jq++) {
            int key = colhalf * 64 + jq * 4;
            int chunk = key >> 5;
            uint32_t bo = (uint32_t)(row * 128 + (key & 31) * 4);
            uint32_t sw = bo ^ ((bo >> 3) & 0x70);
            char* base = (chunk < 2) ? atl + 32768 + chunk * 16384
                                     : atl + 65536 + (chunk - 2) * 16384;
            uint4 o;
            o.x = sr[jq * 4 + 0]; o.y = sr[jq * 4 + 1];
            o.z = sr[jq * 4 + 2]; o.w = sr[jq * 4 + 3];
            *(uint4*)(base + sw) = o;
        }
        TC_FENCE_BEFORE();
        __syncthreads();
        l_run = l_run * alpha + rsum2[row] + rsum2[128 + row];

        // ---- MMA2: O = P V^T (fresh each tile) ----
        if (wid == 0 && elect_one()) {
            TC_FENCE_AFTER();
#pragma unroll
            for (int c = 0; c < 4; c++) {
                uint64_t pd = make_desc((c < 2) ? abase + 32768 + c * 16384
                                                : abase + 65536 + (c - 2) * 16384);
                uint64_t vd = make_desc(abase + 98304 + c * 8192);
#pragma unroll
                for (int k4 = 0; k4 < 4; k4++)
                    mma_tf32_ss(tmem_base + 128, pd + k4 * 2, vd + k4 * 2, IDESC_O,
                                (c > 0 || k4 > 0) ? 1u : 0u);
            }
            TC_COMMIT(mbarO);
        }
        MBAR_WAIT(mbarO, phO); phO ^= 1;
        TC_FENCE_AFTER();

        uint32_t orr[32];
        TC_LD32X32(orr, tmem_base + 128 + 32 * colhalf);
        TC_WAIT_LD();
#pragma unroll
        for (int k = 0; k < 32; k++) acc[k] += __uint_as_float(orr[k]);
        TC_FENCE_BEFORE();
        __syncthreads();   // all O reads + P reads done before next-tile smem overwrite
    }

    // ---- epilogue ----
    {
        float invl = 1.f / l_run;
        int b = bh >> 4, h = bh & 15;
        float* dst = g_O + ((size_t)b * PN + n0 + row) * PE + h * 64 + colhalf * 32;
#pragma unroll
        for (int k = 0; k < 32; k += 4) {
            float4 v;
            v.x = acc[k + 0] * invl; v.y = acc[k + 1] * invl;
            v.z = acc[k + 2] * invl; v.w = acc[k + 3] * invl;
            *(float4*)(dst + k) = v;
        }
    }

    __syncthreads();
    if (wid == 0) {
        if (elect_one()) { MBAR_INVAL(mbarS); MBAR_INVAL(mbarO); }
        TC_RELINQ();
        TC_DEALLOC(tmem_base, 256);
    }
#else
    // ------------------- FFMA fallback (two 64-row passes) -------------------
    float* Qs = (float*)smem;       // 4096 floats
    float* KP = Qs + 64 * 64;       // stride 65
    float* Vs = KP + 64 * 65;       // 4096 floats

    const int tx = tid & 15;
    const int ty = tid >> 4;

    for (int qs = 0; qs < 2; qs++) {
        const int n0 = blockIdx.x * 128 + qs * 64;

        for (int idx = tid; idx < 64 * 64; idx += 256) {
            int r = idx >> 6, d = idx & 63;
            Qs[r * 64 + d] = Qg[baseQK + (size_t)(n0 + r) * PD + d];
        }
        float o[4][4], m_i[4], l_i[4];
#pragma unroll
        for (int i = 0; i < 4; i++) {
            m_i[i] = -INFINITY; l_i[i] = 0.f;
#pragma unroll
            for (int j = 0; j < 4; j++) o[i][j] = 0.f;
        }
        __syncthreads();

        for (int kt = 0; kt < PN / 64; kt++) {
            int k0 = kt * 64;
            for (int idx = tid; idx < 64 * 64; idx += 256) {
                int r = idx >> 6, d = idx & 63;
                KP[r * 65 + d] = Kg[baseQK + (size_t)(k0 + r) * PD + d];
                Vs[r * 64 + d] = Vtg[baseVt + (size_t)d * PN + (k0 + r)];
            }
            __syncthreads();

            float s[4][4];
#pragma unroll
            for (int i = 0; i < 4; i++)
#pragma unroll
                for (int j = 0; j < 4; j++) s[i][j] = 0.f;

            for (int k = 0; k < 64; k += 4) {
                float q[4][4];
#pragma unroll
                for (int i = 0; i < 4; i++) {
                    float4 t = *(const float4*)&Qs[(4 * ty + i) * 64 + k];
                    q[i][0] = t.x; q[i][1] = t.y; q[i][2] = t.z; q[i][3] = t.w;
                }
#pragma unroll
                for (int kk = 0; kk < 4; kk++) {
                    float kv[4];
#pragma unroll
                    for (int j = 0; j < 4; j++)
                        kv[j] = KP[(4 * tx + j) * 65 + k + kk];
#pragma unroll
                    for (int i = 0; i < 4; i++)
#pragma unroll
                        for (int j = 0; j < 4; j++)
                            s[i][j] += q[i][kk] * kv[j];
                }
            }

            float mnew[4], alpha[4];
#pragma unroll
            for (int i = 0; i < 4; i++) {
                float mt = s[i][0];
#pragma unroll
                for (int j = 1; j < 4; j++) mt = fmaxf(mt, s[i][j]);
                mt *= scale;
#pragma unroll
                for (int off = 8; off >= 1; off >>= 1)
                    mt = fmaxf(mt, __shfl_xor_sync(0xffffffffu, mt, off));
                mnew[i] = fmaxf(m_i[i], mt);
                alpha[i] = __expf(m_i[i] - mnew[i]);
                m_i[i] = mnew[i];
            }
            float p[4][4];
#pragma unroll
            for (int i = 0; i < 4; i++) {
                float lt = 0.f;
#pragma unroll
                for (int j = 0; j < 4; j++) {
                    p[i][j] = __expf(s[i][j] * scale - mnew[i]);
                    lt += p[i][j];
                }
#pragma unroll
                for (int off = 8; off >= 1; off >>= 1)
                    lt += __shfl_xor_sync(0xffffffffu, lt, off);
                l_i[i] = l_i[i] * alpha[i] + lt;
#pragma unroll
                for (int j = 0; j < 4; j++) o[i][j] *= alpha[i];
            }

            __syncthreads();
#pragma unroll
            for (int i = 0; i < 4; i++)
#pragma unroll
                for (int j = 0; j < 4; j++)
                    KP[(4 * ty + i) * 65 + 4 * tx + j] = p[i][j];
            __syncthreads();

            for (int jj = 0; jj < 64; jj++) {
                float pv[4];
#pragma unroll
                for (int i = 0; i < 4; i++) pv[i] = KP[(4 * ty + i) * 65 + jj];
                float4 vv = *(const float4*)&Vs[jj * 64 + 4 * tx];
#pragma unroll
                for (int i = 0; i < 4; i++) {
                    o[i][0] += pv[i] * vv.x;
                    o[i][1] += pv[i] * vv.y;
                    o[i][2] += pv[i] * vv.z;
                    o[i][3] += pv[i] * vv.w;
                }
            }
            __syncthreads();
        }

        int b = bh / PH, h = bh % PH;
#pragma unroll
        for (int i = 0; i < 4; i++) {
            float inv_l = 1.f / l_i[i];
            int n = n0 + 4 * ty + i;
            float4 v;
            v.x = o[i][0] * inv_l; v.y = o[i][1] * inv_l;
            v.z = o[i][2] * inv_l; v.w = o[i][3] * inv_l;
            *(float4*)&g_O[((size_t)b * PN + n) * PE + h * 64 + 4 * tx] = v;
        }
        __syncthreads();
    }
#endif
    (void)Og;
}

// ---------------------------------------------------------------------------
extern "C" void kernel_launch(void* const* d_in, const int* in_sizes, int n_in,
                              void* d_out, int out_size)
{
    const float* x      = (const float*)d_in[0];
    const float* w_qkv  = (const float*)d_in[1];
    const float* b_qkv  = (const float*)d_in[2];
    const float* w_proj = (const float*)d_in[3];
    const float* b_proj = (const float*)d_in[4];
    float* out = (float*)d_out;

    cudaFuncSetAttribute(gemm_any<0>,
                         cudaFuncAttributeMaxDynamicSharedMemorySize, GEMM_SMEM);
    cudaFuncSetAttribute(gemm_any<1>,
                         cudaFuncAttributeMaxDynamicSharedMemorySize, GEMM_SMEM);
    cudaFuncSetAttribute(flash_attn,
                         cudaFuncAttributeMaxDynamicSharedMemorySize, FA_SMEM);

    // 1) QKV projection + scatter (V stored transposed)
    {
        dim3 grid(QKV_COLS / 128, M_TOK / 128);
        gemm_any<0><<<grid, 256, GEMM_SMEM>>>(x, w_qkv, b_qkv, nullptr,
                                              QKV_COLS, PE);
    }

    // 2) Flash attention
    {
        dim3 grid(PN / 128, PB * PH);
        float *Qp, *Kp, *Vp, *Op;
        cudaGetSymbolAddress((void**)&Qp, g_Q);
        cudaGetSymbolAddress((void**)&Kp, g_K);
        cudaGetSymbolAddress((void**)&Vp, g_V);
        cudaGetSymbolAddress((void**)&Op, g_O);
        flash_attn<<<grid, 256, FA_SMEM>>>(Qp, Kp, Vp, Op);
    }

    // 3) Output projection
    {
        float* Op;
        cudaGetSymbolAddress((void**)&Op, g_O);
        dim3 grid(PE / 128, M_TOK / 128);
        gemm_any<1><<<grid, 256, GEMM_SMEM>>>(Op, w_proj, b_proj, out,
                                              PE, PE);
    }
}

// round 12
// speedup vs baseline: 4.3721x; 1.1699x over previous
#include <cuda_runtime.h>
#include <math.h>
#include <stdint.h>

// Problem constants
#define PB 2
#define PN 2048
#define PE 1024
#define PH 16
#define PD 64
#define M_TOK (PB * PN)        // 4096 tokens
#define QKV_COLS (3 * PE)      // 3072

// Does this compilation pass support tcgen05 (arch-specific sm_10xa target)?
#if defined(__CUDA_ARCH_FEAT_SM103_ALL) || defined(__CUDA_ARCH_FEAT_SM101_ALL) || defined(__CUDA_ARCH_FEAT_SM100_ALL)
#define HAS_TC 1
#else
#define HAS_TC 0
#endif

// Scratch (no cudaMalloc allowed)
__device__ float g_Q[PB * PH * PN * PD];   // [B,H,N,D] (tf32-rounded)
__device__ float g_K[PB * PH * PN * PD];   // [B,H,N,D] (tf32-rounded)
__device__ float g_V[PB * PH * PN * PD];   // [B,H,D,N] TRANSPOSED (tf32-rounded)
__device__ float g_O[M_TOK * PE];          // [B,N,E] pre-projection (tf32-rounded)
__device__ float g_xc[M_TOK * PE];         // x, tf32-rounded
__device__ float g_wq[QKV_COLS * PE];      // w_qkv, tf32-rounded
__device__ float g_wp[PE * PE];            // w_proj, tf32-rounded

// ===========================================================================
// PTX helpers
// ===========================================================================
__device__ __forceinline__ uint32_t smem_u32(const void* p) {
    uint32_t a;
    asm("{ .reg .u64 t; cvta.to.shared.u64 t, %1; cvt.u32.u64 %0, t; }"
        : "=r"(a) : "l"(p));
    return a;
}
__device__ __forceinline__ uint32_t f2tf32(float f) {
    uint32_t r;
    asm("cvt.rna.tf32.f32 %0, %1;" : "=r"(r) : "f"(f));
    return r;
}
__device__ __forceinline__ float roundtf(float f) {
    return __uint_as_float(f2tf32(f));
}
#define CP_ASYNC16(dst, src) asm volatile("cp.async.ca.shared.global [%0], [%1], 16;" :: "r"((uint32_t)(dst)), "l"(src) : "memory")
#define CP_COMMIT()          asm volatile("cp.async.commit_group;" ::: "memory")
#define CP_WAIT0()           asm volatile("cp.async.wait_group 0;" ::: "memory")

#if HAS_TC
__device__ __forceinline__ uint32_t elect_one() {
    uint32_t pred;
    asm volatile("{\n\t.reg .pred p;\n\telect.sync _|p, 0xFFFFFFFF;\n\t"
                 "selp.b32 %0, 1, 0, p;\n\t}" : "=r"(pred));
    return pred;
}
#define TC_ALLOC(sm, n)  asm volatile("tcgen05.alloc.cta_group::1.sync.aligned.shared::cta.b32 [%0], %1;" :: "r"((uint32_t)(sm)), "r"((uint32_t)(n)) : "memory")
#define TC_DEALLOC(t, n) asm volatile("tcgen05.dealloc.cta_group::1.sync.aligned.b32 %0, %1;" :: "r"(t), "r"((uint32_t)(n)))
#define TC_RELINQ()      asm volatile("tcgen05.relinquish_alloc_permit.cta_group::1.sync.aligned;")
#define TC_COMMIT(mb)    asm volatile("tcgen05.commit.cta_group::1.mbarrier::arrive::one.shared::cluster.b64 [%0];" :: "r"((uint32_t)(mb)) : "memory")
#define TC_FENCE_AFTER() asm volatile("tcgen05.fence::after_thread_sync;" ::: "memory")
#define TC_FENCE_BEFORE() asm volatile("tcgen05.fence::before_thread_sync;" ::: "memory")
#define TC_WAIT_LD()     asm volatile("tcgen05.wait::ld.sync.aligned;" ::: "memory")
#define FENCE_PROXY()    asm volatile("fence.proxy.async.shared::cta;" ::: "memory")
#define MBAR_INIT(mb, c) asm volatile("mbarrier.init.shared.b64 [%0], %1;" :: "r"((uint32_t)(mb)), "r"((uint32_t)(c)) : "memory")
#define MBAR_INVAL(mb)   asm volatile("mbarrier.inval.shared.b64 [%0];" :: "r"((uint32_t)(mb)) : "memory")

#define MBAR_WAIT(mb, ph) do {                                             \
    uint32_t _m = (uint32_t)(mb); uint32_t _p = (uint32_t)(ph); uint32_t _d;\
    asm volatile("{\n\t.reg .pred p;\n\t"                                  \
        "mbarrier.try_wait.parity.acquire.cta.shared::cta.b64 p, [%1], %2;\n\t" \
        "selp.b32 %0, 1, 0, p;\n\t}" : "=r"(_d) : "r"(_m), "r"(_p) : "memory"); \
    if (!_d) {                                                             \
        asm volatile("{\n\t.reg .pred P1;\n\t"                             \
            "WL_%=:\n\t"                                                   \
            "mbarrier.try_wait.parity.acquire.cta.shared::cta.b64 P1, [%0], %1, 0x989680;\n\t" \
            "@P1 bra.uni WD_%=;\n\t"                                       \
            "bra.uni WL_%=;\n\t"                                           \
            "WD_%=:\n\t}" :: "r"(_m), "r"(_p) : "memory");                 \
    }                                                                      \
} while (0)

#define TC_LD32X32(r, ta)                                                  \
    asm volatile("tcgen05.ld.sync.aligned.32x32b.x32.b32 "                 \
        "{%0, %1, %2, %3, %4, %5, %6, %7, "                                \
        " %8, %9, %10, %11, %12, %13, %14, %15, "                          \
        " %16, %17, %18, %19, %20, %21, %22, %23, "                        \
        " %24, %25, %26, %27, %28, %29, %30, %31}, [%32];"                 \
        : "=r"((r)[0]),  "=r"((r)[1]),  "=r"((r)[2]),  "=r"((r)[3]),       \
          "=r"((r)[4]),  "=r"((r)[5]),  "=r"((r)[6]),  "=r"((r)[7]),       \
          "=r"((r)[8]),  "=r"((r)[9]),  "=r"((r)[10]), "=r"((r)[11]),      \
          "=r"((r)[12]), "=r"((r)[13]), "=r"((r)[14]), "=r"((r)[15]),      \
          "=r"((r)[16]), "=r"((r)[17]), "=r"((r)[18]), "=r"((r)[19]),      \
          "=r"((r)[20]), "=r"((r)[21]), "=r"((r)[22]), "=r"((r)[23]),      \
          "=r"((r)[24]), "=r"((r)[25]), "=r"((r)[26]), "=r"((r)[27]),      \
          "=r"((r)[28]), "=r"((r)[29]), "=r"((r)[30]), "=r"((r)[31])       \
        : "r"(ta))

// SW128 K-major smem descriptor: layout=2, version=1, SBO=64, LBO=1
__device__ __forceinline__ uint64_t make_desc(uint32_t base) {
    uint64_t d = (uint64_t)2 << 61 | (uint64_t)1 << 46 |
                 (uint64_t)64 << 32 | (uint64_t)1 << 16;
    return d | ((uint64_t)(base >> 4) & 0x3FFF);
}

__device__ __forceinline__ void mma_tf32_ss(uint32_t d, uint64_t ad, uint64_t bd,
                                            uint32_t idesc, uint32_t en) {
    asm volatile("{\n\t.reg .pred p;\n\tsetp.ne.u32 p, %5, 0;\n\t"
                 "tcgen05.mma.cta_group::1.kind::tf32 [%0], %1, %2, %3, "
                 "{%4, %4, %4, %4}, p;\n\t}"
                 :: "r"(d), "l"(ad), "l"(bd), "r"(idesc), "r"(0u), "r"(en)
                 : "memory");
}
#endif  // HAS_TC

// ===========================================================================
// Prep: round inputs to tf32 once (saves cvt+register pass in GEMM mainloops)
// ===========================================================================
__global__ void prep_convert(const float* __restrict__ x,
                             const float* __restrict__ wq,
                             const float* __restrict__ wp)
{
    const int g = blockIdx.x * blockDim.x + threadIdx.x;
    const int stride = gridDim.x * blockDim.x;
    const int n1 = M_TOK * PE / 4;
    const int n2 = QKV_COLS * PE / 4;
    const int n3 = PE * PE / 4;
    for (int i = g; i < n1; i += stride) {
        float4 v = ((const float4*)x)[i];
        v.x = roundtf(v.x); v.y = roundtf(v.y);
        v.z = roundtf(v.z); v.w = roundtf(v.w);
        ((float4*)g_xc)[i] = v;
    }
    for (int i = g; i < n2; i += stride) {
        float4 v = ((const float4*)wq)[i];
        v.x = roundtf(v.x); v.y = roundtf(v.y);
        v.z = roundtf(v.z); v.w = roundtf(v.w);
        ((float4*)g_wq)[i] = v;
    }
    for (int i = g; i < n3; i += stride) {
        float4 v = ((const float4*)wp)[i];
        v.x = roundtf(v.x); v.y = roundtf(v.y);
        v.z = roundtf(v.z); v.w = roundtf(v.w);
        ((float4*)g_wp)[i] = v;
    }
}

// ===========================================================================
// GEMM-NT: C[M,Ncols] = A[M,K] * Bm[Ncols,K]^T (+bias). Operands pre-rounded.
// 128x128 tile per CTA, 256 threads, grid (Ncols/128, M/128).
// TC path: cp.async double-buffered SW128 stages -> tcgen05 tf32 SS MMA.
// EPI 0: scatter into g_Q/g_K (N,D) + g_V (D,N) with bias, tf32-rounded.
// EPI 1: plain store + bias.
// ===========================================================================
#define IDESC_TF32 ((1u << 4) | (2u << 7) | (2u << 10) | ((128u / 8) << 17) | ((128u / 16) << 24))
#define GEMM_SMEM 69632

template <int EPI>
__global__ void __launch_bounds__(256, 2) __cluster_dims__(1, 1, 1)
gemm_any(const float* __restrict__ A, const float* __restrict__ Bm,
         const float* __restrict__ bias, float* __restrict__ C,
         int Ncols, int K)
{
    extern __shared__ char smem[];
    const int tid = threadIdx.x;
    const int m0 = blockIdx.y * 128;
    const int n0 = blockIdx.x * 128;

#if HAS_TC
    const uint32_t smem_base = smem_u32(smem);
    const int wid = tid >> 5;
    const int lid = tid & 31;
    const uint32_t abase = (smem_base + 32 + 1023) & ~1023u;
    const uint32_t mbar0 = smem_base + 8;
    const uint32_t mbar1 = smem_base + 16;

    if (wid == 0) {
        TC_ALLOC(smem_base, 128);
        if (elect_one()) { MBAR_INIT(mbar0, 1); MBAR_INIT(mbar1, 1); }
    }
    __syncthreads();
    uint32_t tmem_base;
    asm volatile("ld.shared.b32 %0, [%1];" : "=r"(tmem_base) : "r"(smem_base));

    const int nchunks = K / 32;
    int phase[2] = {0, 0};

    for (int c = 0; c < nchunks; c++) {
        const int s = c & 1;
        if (c >= 2) {
            MBAR_WAIT(s ? mbar1 : mbar0, phase[s]);
            phase[s] ^= 1;
        }
        const uint32_t stage = abase + s * 32768;
        const int kt = c * 32;
#pragma unroll
        for (int t = 0; t < 8; t++) {
            int idx = tid + t * 256;            // 0..2047 float4 slots
            int isB = idx >> 10;
            int r = (idx & 1023) >> 3;
            int q = idx & 7;
            const float* src = (isB ? Bm + (size_t)(n0 + r) * K
                                    : A + (size_t)(m0 + r) * K) + kt + 4 * q;
            uint32_t bo = (uint32_t)(r * 128 + q * 16);
            uint32_t sw = bo ^ ((bo >> 3) & 0x70);
            CP_ASYNC16(stage + (isB ? 16384u : 0u) + sw, src);
        }
        CP_COMMIT();
        CP_WAIT0();
        __syncthreads();
        if (wid == 0 && elect_one()) {
            FENCE_PROXY();
            uint64_t ad = make_desc(stage);
            uint64_t bd = make_desc(stage + 16384);
#pragma unroll
            for (int k4 = 0; k4 < 4; k4++)
                mma_tf32_ss(tmem_base, ad + k4 * 2, bd + k4 * 2, IDESC_TF32,
                            (c > 0 || k4 > 0) ? 1u : 0u);
            TC_COMMIT(s ? mbar1 : mbar0);
        }
    }
    MBAR_WAIT(mbar0, phase[0]);
    MBAR_WAIT(mbar1, phase[1]);
    TC_FENCE_AFTER();

    float* eps = (float*)(smem + (abase - smem_base));
    const int ESTRIDE = 132;
    if (wid < 4) {
#pragma unroll
        for (int base = 0; base < 128; base += 32) {
            uint32_t r[32];
            TC_LD32X32(r, tmem_base + base);
            TC_WAIT_LD();
#pragma unroll
            for (int cc = 0; cc < 32; cc++)
                eps[(wid * 32 + lid) * ESTRIDE + base + cc] = __uint_as_float(r[cc]);
        }
        TC_FENCE_BEFORE();
    }
    __syncthreads();

    if (EPI == 1) {
        for (int idx = tid; idx < 128 * 32; idx += 256) {
            int row = idx >> 5, q = idx & 31;
            float4 v = *(const float4*)&eps[row * ESTRIDE + 4 * q];
            int colg = n0 + 4 * q;
            v.x += bias[colg + 0]; v.y += bias[colg + 1];
            v.z += bias[colg + 2]; v.w += bias[colg + 3];
            *(float4*)(C + (size_t)(m0 + row) * Ncols + colg) = v;
        }
    } else {
        // Q/K scatter (d-contiguous, partially coalesced), tf32-rounded
        for (int idx = tid; idx < 128 * 128; idx += 256) {
            int row = idx >> 7, col = idx & 127;
            int colg = n0 + col;
            int which = colg % 3;
            if (which == 2) continue;    // V handled below
            float v = eps[row * ESTRIDE + col] + bias[colg];
            int rest = colg / 3;         // h*64 + d
            int h = rest >> 6;
            int d = rest & 63;
            int tok = m0 + row;
            int bb = tok >> 11;
            int n = tok & 2047;
            float* out = (which == 0) ? g_Q : g_K;
            out[(((size_t)(bb * PH + h)) * PN + n) * PD + d] = roundtf(v);
        }
        // V scatter: coalesced along n (one col per warp, lanes sweep rows)
        {
            int bb = m0 >> 11;
            int nbase = m0 & 2047;
            int c0 = ((2 - (n0 % 3)) % 3 + 3) % 3;   // first col with which==2
            for (int j = wid; c0 + 3 * j < 128; j += 8) {
                int col = c0 + 3 * j;
                int colg = n0 + col;
                int rest = colg / 3;
                int h = rest >> 6;
                int d = rest & 63;
                float bv = bias[colg];
                float* dstp = g_V + (((size_t)(bb * PH + h)) * PD + d) * PN + nbase;
                for (int r = lid; r < 128; r += 32)
                    dstp[r] = roundtf(eps[r * ESTRIDE + col] + bv);
            }
        }
    }

    __syncthreads();
    if (wid == 0) {
        if (elect_one()) { MBAR_INVAL(mbar0); MBAR_INVAL(mbar1); }
        TC_RELINQ();
        TC_DEALLOC(tmem_base, 128);
    }
#else
    // ------------------------- FFMA fallback path -------------------------
    float (*As)[132] = reinterpret_cast<float(*)[132]>(smem);
    float (*Bs)[132] = reinterpret_cast<float(*)[132]>(smem + 16 * 132 * sizeof(float));

    const int tx = tid & 15;
    const int ty = tid >> 4;

    float acc[8][8];
#pragma unroll
    for (int i = 0; i < 8; i++)
#pragma unroll
        for (int j = 0; j < 8; j++) acc[i][j] = 0.f;

    for (int kt = 0; kt < K; kt += 16) {
#pragma unroll
        for (int e = 0; e < 2; e++) {
            int idx = tid + e * 256;
            int row = idx >> 2;
            int kq  = (idx & 3) << 2;
            float4 a = *(const float4*)(A + (size_t)(m0 + row) * K + kt + kq);
            As[kq + 0][row] = a.x; As[kq + 1][row] = a.y;
            As[kq + 2][row] = a.z; As[kq + 3][row] = a.w;
            float4 b = *(const float4*)(Bm + (size_t)(n0 + row) * K + kt + kq);
            Bs[kq + 0][row] = b.x; Bs[kq + 1][row] = b.y;
            Bs[kq + 2][row] = b.z; Bs[kq + 3][row] = b.w;
        }
        __syncthreads();
#pragma unroll
        for (int kk = 0; kk < 16; kk++) {
            float a[8], b[8];
            *(float4*)(a + 0) = *(const float4*)&As[kk][4 * ty];
            *(float4*)(a + 4) = *(const float4*)&As[kk][64 + 4 * ty];
            *(float4*)(b + 0) = *(const float4*)&Bs[kk][4 * tx];
            *(float4*)(b + 4) = *(const float4*)&Bs[kk][64 + 4 * tx];
#pragma unroll
            for (int i = 0; i < 8; i++)
#pragma unroll
                for (int j = 0; j < 8; j++) acc[i][j] += a[i] * b[j];
        }
        __syncthreads();
    }

#pragma unroll
    for (int bi = 0; bi < 2; bi++) {
#pragma unroll
        for (int i = 0; i < 4; i++) {
            int row = m0 + bi * 64 + 4 * ty + i;
#pragma unroll
            for (int bj = 0; bj < 2; bj++) {
                if (EPI == 1) {
                    int col = n0 + bj * 64 + 4 * tx;
                    float4 v;
                    v.x = acc[bi * 4 + i][bj * 4 + 0] + bias[col + 0];
                    v.y = acc[bi * 4 + i][bj * 4 + 1] + bias[col + 1];
                    v.z = acc[bi * 4 + i][bj * 4 + 2] + bias[col + 2];
                    v.w = acc[bi * 4 + i][bj * 4 + 3] + bias[col + 3];
                    *(float4*)(C + (size_t)row * Ncols + col) = v;
                } else {
#pragma unroll
                    for (int j = 0; j < 4; j++) {
                        int col = n0 + bj * 64 + 4 * tx + j;
                        float v = acc[bi * 4 + i][bj * 4 + j] + bias[col];
                        int which = col % 3;
                        int rest  = col / 3;
                        int h = rest >> 6;
                        int d = rest & 63;
                        int bb = row >> 11;
                        int n  = row & 2047;
                        size_t dst;
                        float* out;
                        if (which == 0)      { out = g_Q; dst = (((size_t)(bb * PH + h)) * PN + n) * PD + d; }
                        else if (which == 1) { out = g_K; dst = (((size_t)(bb * PH + h)) * PN + n) * PD + d; }
                        else                 { out = g_V; dst = (((size_t)(bb * PH + h)) * PD + d) * PN + n; }
                        out[dst] = v;
                    }
                }
            }
        }
    }
#endif
}

// ===========================================================================
// Flash attention. TC path: tcgen05 tf32, 128q x 128k tiles, 256 threads.
//   TMEM: S at cols 0..127, O at cols 128..191 (alloc 256).
//   smem tiles (1024-aligned): Qs 2x[128][32] | Ks/P01 | P23 | Vt 4x[64][32]
// Loads via cp.async (operands pre-rounded to tf32 by producer epilogues).
// Fallback: FFMA, two 64-row passes. Both read g_V TRANSPOSED [B,H,D,N].
// Grid (PN/128, PB*PH), 256 threads, dynamic smem FA_SMEM.
// ===========================================================================
#define FA_SMEM 136704
#define IDESC_S ((1u << 4) | (2u << 7) | (2u << 10) | ((128u / 8) << 17) | ((128u / 16) << 24))
#define IDESC_O ((1u << 4) | (2u << 7) | (2u << 10) | ((64u / 8) << 17) | ((128u / 16) << 24))

__global__ void __launch_bounds__(256, 1)
flash_attn(const float* __restrict__ Qg, const float* __restrict__ Kg,
           const float* __restrict__ Vtg, float* __restrict__ Og)
{
    extern __shared__ char smem[];
    const int tid = threadIdx.x;
    const int bh = blockIdx.y;
    const size_t baseQK = (size_t)bh * PN * PD;
    const size_t baseVt = (size_t)bh * PD * PN;
    const float scale = 0.125f;

#if HAS_TC
    const uint32_t smem_base = smem_u32(smem);
    const int wid = tid >> 5;
    const int lid = tid & 31;
    const int row = (wid & 3) * 32 + lid;   // query row within tile (= TMEM lane)
    const int colhalf = wid >> 2;           // 0: cols 0-63, 1: cols 64-127
    const int n0 = blockIdx.x * 128;

    const uint32_t mbarS = smem_base + 8;
    const uint32_t mbarO = smem_base + 16;
    float* rmax2 = (float*)(smem + 64);         // [2][128]
    float* rsum2 = (float*)(smem + 64 + 1024);  // [2][128]
    const uint32_t abase = (smem_base + 4096 + 1023) & ~1023u;
    char* atl = smem + (abase - smem_base);
    // Qs: +0 (2x16384) | Ks/P01: +32768 | P23: +65536 | Vt: +98304 (4x8192)

    if (wid == 0) {
        TC_ALLOC(smem_base, 256);
        if (elect_one()) { MBAR_INIT(mbarS, 1); MBAR_INIT(mbarO, 1); }
    }
    __syncthreads();
    uint32_t tmem_base;
    asm volatile("ld.shared.b32 %0, [%1];" : "=r"(tmem_base) : "r"(smem_base));

    // Load Q tile once: [128 rows][64 d] -> 2 SW128 chunks of [128][32]
#pragma unroll
    for (int t = 0; t < 8; t++) {
        int idx = tid + t * 256;            // float4 slots (16 per row)
        int r = idx >> 4;
        int q = idx & 15;
        const float* src = Qg + baseQK + (size_t)(n0 + r) * PD + 4 * q;
        uint32_t bo = (uint32_t)(r * 128 + (q & 7) * 16);
        uint32_t sw = bo ^ ((bo >> 3) & 0x70);
        CP_ASYNC16(abase + (q >> 3) * 16384 + sw, src);
    }
    CP_COMMIT();

    float acc[32];
#pragma unroll
    for (int k = 0; k < 32; k++) acc[k] = 0.f;
    float m_run = -INFINITY, l_run = 0.f;
    int phS = 0, phO = 0;

    for (int kt = 0; kt < PN / 128; kt++) {
        const int k0 = kt * 128;
        // ---- load K tile [128 keys][64 d] -> 2 chunks of [128][32] ----
#pragma unroll
        for (int t = 0; t < 8; t++) {
            int idx = tid + t * 256;
            int r = idx >> 4;
            int q = idx & 15;
            const float* src = Kg + baseQK + (size_t)(k0 + r) * PD + 4 * q;
            uint32_t bo = (uint32_t)(r * 128 + (q & 7) * 16);
            uint32_t sw = bo ^ ((bo >> 3) & 0x70);
            CP_ASYNC16(abase + 32768 + (q >> 3) * 16384 + sw, src);
        }
        // ---- load Vt tile [64 d][128 keys] -> 4 chunks of [64][32] ----
#pragma unroll
        for (int t = 0; t < 8; t++) {
            int idx = tid + t * 256;    // 0..2047
            int d = idx >> 5;           // 0..63
            int qk = idx & 31;          // float4 within row (32 per row)
            const float* src = Vtg + baseVt + (size_t)d * PN + k0 + 4 * qk;
            uint32_t bo = (uint32_t)(d * 128 + (qk & 7) * 16);
            uint32_t sw = bo ^ ((bo >> 3) & 0x70);
            CP_ASYNC16(abase + 98304 + (qk >> 3) * 8192 + sw, src);
        }
        CP_COMMIT();
        CP_WAIT0();
        __syncthreads();

        // ---- MMA1: S = Q K^T ----
        if (wid == 0 && elect_one()) {
            FENCE_PROXY();
            TC_FENCE_AFTER();
#pragma unroll
            for (int c = 0; c < 2; c++) {
                uint64_t qd = make_desc(abase + c * 16384);
                uint64_t kd = make_desc(abase + 32768 + c * 16384);
#pragma unroll
                for (int k4 = 0; k4 < 4; k4++)
                    mma_tf32_ss(tmem_base, qd + k4 * 2, kd + k4 * 2, IDESC_S,
                                (c > 0 || k4 > 0) ? 1u : 0u);
            }
            TC_COMMIT(mbarS);
        }
        MBAR_WAIT(mbarS, phS); phS ^= 1;
        TC_FENCE_AFTER();

        // ---- softmax (thread owns half of S row `row`) ----
        uint32_t sr[64];
        TC_LD32X32(sr, tmem_base + 64 * colhalf);
        TC_LD32X32(sr + 32, tmem_base + 64 * colhalf + 32);
        TC_WAIT_LD();

        float mloc = -INFINITY;
#pragma unroll
        for (int j = 0; j < 64; j++) mloc = fmaxf(mloc, __uint_as_float(sr[j]));
        mloc *= scale;
        rmax2[colhalf * 128 + row] = mloc;
        __syncthreads();
        float mnew = fmaxf(m_run, fmaxf(rmax2[row], rmax2[128 + row]));
        float alpha = __expf(m_run - mnew);
        m_run = mnew;

        float lsum = 0.f;
#pragma unroll
        for (int j = 0; j < 64; j++) {
            float p = __expf(__uint_as_float(sr[j]) * scale - mnew);
            lsum += p;
            sr[j] = f2tf32(p);
        }
        rsum2[colhalf * 128 + row] = lsum;
#pragma unroll
        for (int k = 0; k < 32; k++) acc[k] *= alpha;

        // ---- store P (tf32) into chunks: keys 64*colhalf..+63 ----
#pragma unroll
        for (int jq = 0; jq < 16; jq++) {
            int key = colhalf * 64 + jq * 4;
            int chunk = key >> 5;
            uint32_t bo = (uint32_t)(row * 128 + (key & 31) * 4);
            uint32_t sw = bo ^ ((bo >> 3) & 0x70);
            char* base = (chunk < 2) ? atl + 32768 + chunk * 16384
                                     : atl + 65536 + (chunk - 2) * 16384;
            uint4 o;
            o.x = sr[jq * 4 + 0]; o.y = sr[jq * 4 + 1];
            o.z = sr[jq * 4 + 2]; o.w = sr[jq * 4 + 3];
            *(uint4*)(base + sw) = o;
        }
        TC_FENCE_BEFORE();
        __syncthreads();
        l_run = l_run * alpha + rsum2[row] + rsum2[128 + row];

        // ---- MMA2: O = P V^T (fresh each tile) ----
        if (wid == 0 && elect_one()) {
            FENCE_PROXY();
            TC_FENCE_AFTER();
#pragma unroll
            for (int c = 0; c < 4; c++) {
                uint64_t pd = make_desc((c < 2) ? abase + 32768 + c * 16384
                                                : abase + 65536 + (c - 2) * 16384);
                uint64_t vd = make_desc(abase + 98304 + c * 8192);
#pragma unroll
                for (int k4 = 0; k4 < 4; k4++)
                    mma_tf32_ss(tmem_base + 128, pd + k4 * 2, vd + k4 * 2, IDESC_O,
                                (c > 0 || k4 > 0) ? 1u : 0u);
            }
            TC_COMMIT(mbarO);
        }
        MBAR_WAIT(mbarO, phO); phO ^= 1;
        TC_FENCE_AFTER();

        uint32_t orr[32];
        TC_LD32X32(orr, tmem_base + 128 + 32 * colhalf);
        TC_WAIT_LD();
#pragma unroll
        for (int k = 0; k < 32; k++) acc[k] += __uint_as_float(orr[k]);
        TC_FENCE_BEFORE();
        __syncthreads();   // all O reads + P reads done before next-tile smem overwrite
    }

    // ---- epilogue (tf32-rounded: feeds proj GEMM) ----
    {
        float invl = 1.f / l_run;
        int b = bh >> 4, h = bh & 15;
        float* dst = g_O + ((size_t)b * PN + n0 + row) * PE + h * 64 + colhalf * 32;
#pragma unroll
        for (int k = 0; k < 32; k += 4) {
            float4 v;
            v.x = roundtf(acc[k + 0] * invl); v.y = roundtf(acc[k + 1] * invl);
            v.z = roundtf(acc[k + 2] * invl); v.w = roundtf(acc[k + 3] * invl);
            *(float4*)(dst + k) = v;
        }
    }

    __syncthreads();
    if (wid == 0) {
        if (elect_one()) { MBAR_INVAL(mbarS); MBAR_INVAL(mbarO); }
        TC_RELINQ();
        TC_DEALLOC(tmem_base, 256);
    }
#else
    // ------------------- FFMA fallback (two 64-row passes) -------------------
    float* Qs = (float*)smem;       // 4096 floats
    float* KP = Qs + 64 * 64;       // stride 65
    float* Vs = KP + 64 * 65;       // 4096 floats

    const int tx = tid & 15;
    const int ty = tid >> 4;

    for (int qs = 0; qs < 2; qs++) {
        const int n0 = blockIdx.x * 128 + qs * 64;

        for (int idx = tid; idx < 64 * 64; idx += 256) {
            int r = idx >> 6, d = idx & 63;
            Qs[r * 64 + d] = Qg[baseQK + (size_t)(n0 + r) * PD + d];
        }
        float o[4][4], m_i[4], l_i[4];
#pragma unroll
        for (int i = 0; i < 4; i++) {
            m_i[i] = -INFINITY; l_i[i] = 0.f;
#pragma unroll
            for (int j = 0; j < 4; j++) o[i][j] = 0.f;
        }
        __syncthreads();

        for (int kt = 0; kt < PN / 64; kt++) {
            int k0 = kt * 64;
            for (int idx = tid; idx < 64 * 64; idx += 256) {
                int r = idx >> 6, d = idx & 63;
                KP[r * 65 + d] = Kg[baseQK + (size_t)(k0 + r) * PD + d];
                Vs[r * 64 + d] = Vtg[baseVt + (size_t)d * PN + (k0 + r)];
            }
            __syncthreads();

            float s[4][4];
#pragma unroll
            for (int i = 0; i < 4; i++)
#pragma unroll
                for (int j = 0; j < 4; j++) s[i][j] = 0.f;

            for (int k = 0; k < 64; k += 4) {
                float q[4][4];
#pragma unroll
                for (int i = 0; i < 4; i++) {
                    float4 t = *(const float4*)&Qs[(4 * ty + i) * 64 + k];
                    q[i][0] = t.x; q[i][1] = t.y; q[i][2] = t.z; q[i][3] = t.w;
                }
#pragma unroll
                for (int kk = 0; kk < 4; kk++) {
                    float kv[4];
#pragma unroll
                    for (int j = 0; j < 4; j++)
                        kv[j] = KP[(4 * tx + j) * 65 + k + kk];
#pragma unroll
                    for (int i = 0; i < 4; i++)
#pragma unroll
                        for (int j = 0; j < 4; j++)
                            s[i][j] += q[i][kk] * kv[j];
                }
            }

            float mnew[4], alpha[4];
#pragma unroll
            for (int i = 0; i < 4; i++) {
                float mt = s[i][0];
#pragma unroll
                for (int j = 1; j < 4; j++) mt = fmaxf(mt, s[i][j]);
                mt *= scale;
#pragma unroll
                for (int off = 8; off >= 1; off >>= 1)
                    mt = fmaxf(mt, __shfl_xor_sync(0xffffffffu, mt, off));
                mnew[i] = fmaxf(m_i[i], mt);
                alpha[i] = __expf(m_i[i] - mnew[i]);
                m_i[i] = mnew[i];
            }
            float p[4][4];
#pragma unroll
            for (int i = 0; i < 4; i++) {
                float lt = 0.f;
#pragma unroll
                for (int j = 0; j < 4; j++) {
                    p[i][j] = __expf(s[i][j] * scale - mnew[i]);
                    lt += p[i][j];
                }
#pragma unroll
                for (int off = 8; off >= 1; off >>= 1)
                    lt += __shfl_xor_sync(0xffffffffu, lt, off);
                l_i[i] = l_i[i] * alpha[i] + lt;
#pragma unroll
                for (int j = 0; j < 4; j++) o[i][j] *= alpha[i];
            }

            __syncthreads();
#pragma unroll
            for (int i = 0; i < 4; i++)
#pragma unroll
                for (int j = 0; j < 4; j++)
                    KP[(4 * ty + i) * 65 + 4 * tx + j] = p[i][j];
            __syncthreads();

            for (int jj = 0; jj < 64; jj++) {
                float pv[4];
#pragma unroll
                for (int i = 0; i < 4; i++) pv[i] = KP[(4 * ty + i) * 65 + jj];
                float4 vv = *(const float4*)&Vs[jj * 64 + 4 * tx];
#pragma unroll
                for (int i = 0; i < 4; i++) {
                    o[i][0] += pv[i] * vv.x;
                    o[i][1] += pv[i] * vv.y;
                    o[i][2] += pv[i] * vv.z;
                    o[i][3] += pv[i] * vv.w;
                }
            }
            __syncthreads();
        }

        int b = bh / PH, h = bh % PH;
#pragma unroll
        for (int i = 0; i < 4; i++) {
            float inv_l = 1.f / l_i[i];
            int n = n0 + 4 * ty + i;
            float4 v;
            v.x = o[i][0] * inv_l; v.y = o[i][1] * inv_l;
            v.z = o[i][2] * inv_l; v.w = o[i][3] * inv_l;
            *(float4*)&g_O[((size_t)b * PN + n) * PE + h * 64 + 4 * tx] = v;
        }
        __syncthreads();
    }
#endif
    (void)Og;
}

// ---------------------------------------------------------------------------
extern "C" void kernel_launch(void* const* d_in, const int* in_sizes, int n_in,
                              void* d_out, int out_size)
{
    const float* x      = (const float*)d_in[0];
    const float* w_qkv  = (const float*)d_in[1];
    const float* b_qkv  = (const float*)d_in[2];
    const float* w_proj = (const float*)d_in[3];
    const float* b_proj = (const float*)d_in[4];
    float* out = (float*)d_out;

    cudaFuncSetAttribute(gemm_any<0>,
                         cudaFuncAttributeMaxDynamicSharedMemorySize, GEMM_SMEM);
    cudaFuncSetAttribute(gemm_any<1>,
                         cudaFuncAttributeMaxDynamicSharedMemorySize, GEMM_SMEM);
    cudaFuncSetAttribute(flash_attn,
                         cudaFuncAttributeMaxDynamicSharedMemorySize, FA_SMEM);

    float *xc, *wq, *wp, *Qp, *Kp, *Vp, *Op;
    cudaGetSymbolAddress((void**)&xc, g_xc);
    cudaGetSymbolAddress((void**)&wq, g_wq);
    cudaGetSymbolAddress((void**)&wp, g_wp);
    cudaGetSymbolAddress((void**)&Qp, g_Q);
    cudaGetSymbolAddress((void**)&Kp, g_K);
    cudaGetSymbolAddress((void**)&Vp, g_V);
    cudaGetSymbolAddress((void**)&Op, g_O);

    // 0) Pre-round inputs to tf32
    prep_convert<<<1024, 256>>>(x, w_qkv, w_proj);

    // 1) QKV projection + scatter (V stored transposed)
    {
        dim3 grid(QKV_COLS / 128, M_TOK / 128);
        gemm_any<0><<<grid, 256, GEMM_SMEM>>>(xc, wq, b_qkv, nullptr,
                                              QKV_COLS, PE);
    }

    // 2) Flash attention
    {
        dim3 grid(PN / 128, PB * PH);
        flash_attn<<<grid, 256, FA_SMEM>>>(Qp, Kp, Vp, Op);
    }

    // 3) Output projection
    {
        float* Og;
        cudaGetSymbolAddress((void**)&Og, g_O);
        dim3 grid(PE / 128, M_TOK / 128);
        gemm_any<1><<<grid, 256, GEMM_SMEM>>>(Og, wp, b_proj, out,
                                              PE, PE);
    }
}

// round 13
// speedup vs baseline: 5.2653x; 1.2043x over previous
#include <cuda_runtime.h>
#include <math.h>
#include <stdint.h>

// Problem constants
#define PB 2
#define PN 2048
#define PE 1024
#define PH 16
#define PD 64
#define M_TOK (PB * PN)        // 4096 tokens
#define QKV_COLS (3 * PE)      // 3072

// Does this compilation pass support tcgen05 (arch-specific sm_10xa target)?
#if defined(__CUDA_ARCH_FEAT_SM103_ALL) || defined(__CUDA_ARCH_FEAT_SM101_ALL) || defined(__CUDA_ARCH_FEAT_SM100_ALL)
#define HAS_TC 1
#else
#define HAS_TC 0
#endif

// Scratch (no cudaMalloc allowed)
__device__ float g_Q[PB * PH * PN * PD];   // [B,H,N,D] (tf32-rounded)
__device__ float g_K[PB * PH * PN * PD];   // [B,H,N,D] (tf32-rounded)
__device__ float g_V[PB * PH * PN * PD];   // [B,H,D,N] TRANSPOSED (tf32-rounded)
__device__ float g_O[M_TOK * PE];          // [B,N,E] pre-projection (tf32-rounded)
__device__ float g_xc[M_TOK * PE];         // x, tf32-rounded
__device__ float g_wq[QKV_COLS * PE];      // w_qkv, tf32-rounded
__device__ float g_wp[PE * PE];            // w_proj, tf32-rounded

// ===========================================================================
// PTX helpers
// ===========================================================================
__device__ __forceinline__ uint32_t smem_u32(const void* p) {
    uint32_t a;
    asm("{ .reg .u64 t; cvta.to.shared.u64 t, %1; cvt.u32.u64 %0, t; }"
        : "=r"(a) : "l"(p));
    return a;
}
__device__ __forceinline__ uint32_t f2tf32(float f) {
    uint32_t r;
    asm("cvt.rna.tf32.f32 %0, %1;" : "=r"(r) : "f"(f));
    return r;
}
__device__ __forceinline__ float roundtf(float f) {
    return __uint_as_float(f2tf32(f));
}
#define CP_ASYNC16(dst, src) asm volatile("cp.async.ca.shared.global [%0], [%1], 16;" :: "r"((uint32_t)(dst)), "l"(src) : "memory")
#define CP_COMMIT()          asm volatile("cp.async.commit_group;" ::: "memory")
#define CP_WAIT0()           asm volatile("cp.async.wait_group 0;" ::: "memory")
#define CP_WAIT1()           asm volatile("cp.async.wait_group 1;" ::: "memory")

#if HAS_TC
__device__ __forceinline__ uint32_t elect_one() {
    uint32_t pred;
    asm volatile("{\n\t.reg .pred p;\n\telect.sync _|p, 0xFFFFFFFF;\n\t"
                 "selp.b32 %0, 1, 0, p;\n\t}" : "=r"(pred));
    return pred;
}
#define TC_ALLOC(sm, n)  asm volatile("tcgen05.alloc.cta_group::1.sync.aligned.shared::cta.b32 [%0], %1;" :: "r"((uint32_t)(sm)), "r"((uint32_t)(n)) : "memory")
#define TC_DEALLOC(t, n) asm volatile("tcgen05.dealloc.cta_group::1.sync.aligned.b32 %0, %1;" :: "r"(t), "r"((uint32_t)(n)))
#define TC_RELINQ()      asm volatile("tcgen05.relinquish_alloc_permit.cta_group::1.sync.aligned;")
#define TC_COMMIT(mb)    asm volatile("tcgen05.commit.cta_group::1.mbarrier::arrive::one.shared::cluster.b64 [%0];" :: "r"((uint32_t)(mb)) : "memory")
#define TC_FENCE_AFTER() asm volatile("tcgen05.fence::after_thread_sync;" ::: "memory")
#define TC_FENCE_BEFORE() asm volatile("tcgen05.fence::before_thread_sync;" ::: "memory")
#define TC_WAIT_LD()     asm volatile("tcgen05.wait::ld.sync.aligned;" ::: "memory")
#define FENCE_PROXY()    asm volatile("fence.proxy.async.shared::cta;" ::: "memory")
#define MBAR_INIT(mb, c) asm volatile("mbarrier.init.shared.b64 [%0], %1;" :: "r"((uint32_t)(mb)), "r"((uint32_t)(c)) : "memory")
#define MBAR_INVAL(mb)   asm volatile("mbarrier.inval.shared.b64 [%0];" :: "r"((uint32_t)(mb)) : "memory")

#define MBAR_WAIT(mb, ph) do {                                             \
    uint32_t _m = (uint32_t)(mb); uint32_t _p = (uint32_t)(ph); uint32_t _d;\
    asm volatile("{\n\t.reg .pred p;\n\t"                                  \
        "mbarrier.try_wait.parity.acquire.cta.shared::cta.b64 p, [%1], %2;\n\t" \
        "selp.b32 %0, 1, 0, p;\n\t}" : "=r"(_d) : "r"(_m), "r"(_p) : "memory"); \
    if (!_d) {                                                             \
        asm volatile("{\n\t.reg .pred P1;\n\t"                             \
            "WL_%=:\n\t"                                                   \
            "mbarrier.try_wait.parity.acquire.cta.shared::cta.b64 P1, [%0], %1, 0x989680;\n\t" \
            "@P1 bra.uni WD_%=;\n\t"                                       \
            "bra.uni WL_%=;\n\t"                                           \
            "WD_%=:\n\t}" :: "r"(_m), "r"(_p) : "memory");                 \
    }                                                                      \
} while (0)

#define TC_LD32X32(r, ta)                                                  \
    asm volatile("tcgen05.ld.sync.aligned.32x32b.x32.b32 "                 \
        "{%0, %1, %2, %3, %4, %5, %6, %7, "                                \
        " %8, %9, %10, %11, %12, %13, %14, %15, "                          \
        " %16, %17, %18, %19, %20, %21, %22, %23, "                        \
        " %24, %25, %26, %27, %28, %29, %30, %31}, [%32];"                 \
        : "=r"((r)[0]),  "=r"((r)[1]),  "=r"((r)[2]),  "=r"((r)[3]),       \
          "=r"((r)[4]),  "=r"((r)[5]),  "=r"((r)[6]),  "=r"((r)[7]),       \
          "=r"((r)[8]),  "=r"((r)[9]),  "=r"((r)[10]), "=r"((r)[11]),      \
          "=r"((r)[12]), "=r"((r)[13]), "=r"((r)[14]), "=r"((r)[15]),      \
          "=r"((r)[16]), "=r"((r)[17]), "=r"((r)[18]), "=r"((r)[19]),      \
          "=r"((r)[20]), "=r"((r)[21]), "=r"((r)[22]), "=r"((r)[23]),      \
          "=r"((r)[24]), "=r"((r)[25]), "=r"((r)[26]), "=r"((r)[27]),      \
          "=r"((r)[28]), "=r"((r)[29]), "=r"((r)[30]), "=r"((r)[31])       \
        : "r"(ta))

// SW128 K-major smem descriptor: layout=2, version=1, SBO=64, LBO=1
__device__ __forceinline__ uint64_t make_desc(uint32_t base) {
    uint64_t d = (uint64_t)2 << 61 | (uint64_t)1 << 46 |
                 (uint64_t)64 << 32 | (uint64_t)1 << 16;
    return d | ((uint64_t)(base >> 4) & 0x3FFF);
}

__device__ __forceinline__ void mma_tf32_ss(uint32_t d, uint64_t ad, uint64_t bd,
                                            uint32_t idesc, uint32_t en) {
    asm volatile("{\n\t.reg .pred p;\n\tsetp.ne.u32 p, %5, 0;\n\t"
                 "tcgen05.mma.cta_group::1.kind::tf32 [%0], %1, %2, %3, "
                 "{%4, %4, %4, %4}, p;\n\t}"
                 :: "r"(d), "l"(ad), "l"(bd), "r"(idesc), "r"(0u), "r"(en)
                 : "memory");
}
#endif  // HAS_TC

// ===========================================================================
// Prep: round inputs to tf32 once
// ===========================================================================
__global__ void prep_convert(const float* __restrict__ x,
                             const float* __restrict__ wq,
                             const float* __restrict__ wp)
{
    const int g = blockIdx.x * blockDim.x + threadIdx.x;
    const int stride = gridDim.x * blockDim.x;
    const int n1 = M_TOK * PE / 4;
    const int n2 = QKV_COLS * PE / 4;
    const int n3 = PE * PE / 4;
    for (int i = g; i < n1; i += stride) {
        float4 v = ((const float4*)x)[i];
        v.x = roundtf(v.x); v.y = roundtf(v.y);
        v.z = roundtf(v.z); v.w = roundtf(v.w);
        ((float4*)g_xc)[i] = v;
    }
    for (int i = g; i < n2; i += stride) {
        float4 v = ((const float4*)wq)[i];
        v.x = roundtf(v.x); v.y = roundtf(v.y);
        v.z = roundtf(v.z); v.w = roundtf(v.w);
        ((float4*)g_wq)[i] = v;
    }
    for (int i = g; i < n3; i += stride) {
        float4 v = ((const float4*)wp)[i];
        v.x = roundtf(v.x); v.y = roundtf(v.y);
        v.z = roundtf(v.z); v.w = roundtf(v.w);
        ((float4*)g_wp)[i] = v;
    }
}

// ===========================================================================
// GEMM-NT: C[M,Ncols] = A[M,K] * Bm[Ncols,K]^T (+bias). Operands pre-rounded.
// 128x128 tile per CTA, 256 threads, grid (Ncols/128, M/128).
// TC path: 3-stage pipelined cp.async -> tcgen05 tf32 SS MMA.
// EPI 0: scatter into g_Q/g_K (N,D) + g_V (D,N) with bias, tf32-rounded.
// EPI 1: plain store + bias.
// ===========================================================================
#define IDESC_TF32 ((1u << 4) | (2u << 7) | (2u << 10) | ((128u / 8) << 17) | ((128u / 16) << 24))
#define GEMM_SMEM 100352

template <int EPI>
__global__ void __launch_bounds__(256, 2) __cluster_dims__(1, 1, 1)
gemm_any(const float* __restrict__ A, const float* __restrict__ Bm,
         const float* __restrict__ bias, float* __restrict__ C,
         int Ncols, int K)
{
    extern __shared__ char smem[];
    const int tid = threadIdx.x;
    const int m0 = blockIdx.y * 128;
    const int n0 = blockIdx.x * 128;

#if HAS_TC
    const uint32_t smem_base = smem_u32(smem);
    const int wid = tid >> 5;
    const int lid = tid & 31;
    const uint32_t abase = (smem_base + 32 + 1023) & ~1023u;

    if (wid == 0) {
        TC_ALLOC(smem_base, 128);
        if (elect_one()) {
            MBAR_INIT(smem_base + 8, 1);
            MBAR_INIT(smem_base + 16, 1);
            MBAR_INIT(smem_base + 24, 1);
        }
    }
    __syncthreads();
    uint32_t tmem_base;
    asm volatile("ld.shared.b32 %0, [%1];" : "=r"(tmem_base) : "r"(smem_base));

    const int nchunks = K / 32;          // >= 3 always here (K=1024)
    uint32_t ph_bits = 0;

    // issue loads for chunk `c` into stage `st`
    auto issue_load = [&](int c, int st) {
        const uint32_t stage = abase + (uint32_t)st * 32768u;
        const int kt = c * 32;
#pragma unroll
        for (int t = 0; t < 8; t++) {
            int idx = tid + t * 256;            // 0..2047 float4 slots
            int isB = idx >> 10;
            int r = (idx & 1023) >> 3;
            int q = idx & 7;
            const float* src = (isB ? Bm + (size_t)(n0 + r) * K
                                    : A + (size_t)(m0 + r) * K) + kt + 4 * q;
            uint32_t bo = (uint32_t)(r * 128 + q * 16);
            uint32_t sw = bo ^ ((bo >> 3) & 0x70);
            CP_ASYNC16(stage + (isB ? 16384u : 0u) + sw, src);
        }
        CP_COMMIT();
    };

    // prologue: chunks 0 and 1
    issue_load(0, 0);
    issue_load(1, 1);

    for (int c = 0; c < nchunks; c++) {
        const int st = c % 3;
        if (c + 1 < nchunks) { CP_WAIT1(); } else { CP_WAIT0(); }
        __syncthreads();
        if (wid == 0 && elect_one()) {
            FENCE_PROXY();
            uint64_t ad = make_desc(abase + (uint32_t)st * 32768u);
            uint64_t bd = make_desc(abase + (uint32_t)st * 32768u + 16384u);
#pragma unroll
            for (int k4 = 0; k4 < 4; k4++)
                mma_tf32_ss(tmem_base, ad + k4 * 2, bd + k4 * 2, IDESC_TF32,
                            (c > 0 || k4 > 0) ? 1u : 0u);
            TC_COMMIT(smem_base + 8 + 8 * st);
        }
        const int nx = c + 2;
        if (nx < nchunks) {
            const int nst = nx % 3;
            if (c >= 1) {
                // wait MMA of chunk c-1 (same stage nst) before overwriting
                MBAR_WAIT(smem_base + 8 + 8 * nst, (ph_bits >> nst) & 1);
                ph_bits ^= (1u << nst);
            }
            issue_load(nx, nst);
        }
    }
    // tail: drain the last three MMA groups
    MBAR_WAIT(smem_base + 8,  ph_bits & 1);
    MBAR_WAIT(smem_base + 16, (ph_bits >> 1) & 1);
    MBAR_WAIT(smem_base + 24, (ph_bits >> 2) & 1);
    TC_FENCE_AFTER();

    float* eps = (float*)(smem + (abase - smem_base));
    const int ESTRIDE = 132;
    if (wid < 4) {
#pragma unroll
        for (int base = 0; base < 128; base += 32) {
            uint32_t r[32];
            TC_LD32X32(r, tmem_base + base);
            TC_WAIT_LD();
#pragma unroll
            for (int cc = 0; cc < 32; cc++)
                eps[(wid * 32 + lid) * ESTRIDE + base + cc] = __uint_as_float(r[cc]);
        }
        TC_FENCE_BEFORE();
    }
    __syncthreads();

    if (EPI == 1) {
        for (int idx = tid; idx < 128 * 32; idx += 256) {
            int row = idx >> 5, q = idx & 31;
            float4 v = *(const float4*)&eps[row * ESTRIDE + 4 * q];
            int colg = n0 + 4 * q;
            v.x += bias[colg + 0]; v.y += bias[colg + 1];
            v.z += bias[colg + 2]; v.w += bias[colg + 3];
            *(float4*)(C + (size_t)(m0 + row) * Ncols + colg) = v;
        }
    } else {
        // Q/K scatter (d-contiguous), tf32-rounded
        for (int idx = tid; idx < 128 * 128; idx += 256) {
            int row = idx >> 7, col = idx & 127;
            int colg = n0 + col;
            int which = colg % 3;
            if (which == 2) continue;    // V handled below
            float v = eps[row * ESTRIDE + col] + bias[colg];
            int rest = colg / 3;         // h*64 + d
            int h = rest >> 6;
            int d = rest & 63;
            int tok = m0 + row;
            int bb = tok >> 11;
            int n = tok & 2047;
            float* out = (which == 0) ? g_Q : g_K;
            out[(((size_t)(bb * PH + h)) * PN + n) * PD + d] = roundtf(v);
        }
        // V scatter: coalesced along n (one col per warp, lanes sweep rows)
        {
            int bb = m0 >> 11;
            int nbase = m0 & 2047;
            int c0 = ((2 - (n0 % 3)) % 3 + 3) % 3;   // first col with which==2
            for (int j = wid; c0 + 3 * j < 128; j += 8) {
                int col = c0 + 3 * j;
                int colg = n0 + col;
                int rest = colg / 3;
                int h = rest >> 6;
                int d = rest & 63;
                float bv = bias[colg];
                float* dstp = g_V + (((size_t)(bb * PH + h)) * PD + d) * PN + nbase;
                for (int r = lid; r < 128; r += 32)
                    dstp[r] = roundtf(eps[r * ESTRIDE + col] + bv);
            }
        }
    }

    __syncthreads();
    if (wid == 0) {
        if (elect_one()) {
            MBAR_INVAL(smem_base + 8);
            MBAR_INVAL(smem_base + 16);
            MBAR_INVAL(smem_base + 24);
        }
        TC_RELINQ();
        TC_DEALLOC(tmem_base, 128);
    }
#else
    // ------------------------- FFMA fallback path -------------------------
    float (*As)[132] = reinterpret_cast<float(*)[132]>(smem);
    float (*Bs)[132] = reinterpret_cast<float(*)[132]>(smem + 16 * 132 * sizeof(float));

    const int tx = tid & 15;
    const int ty = tid >> 4;

    float acc[8][8];
#pragma unroll
    for (int i = 0; i < 8; i++)
#pragma unroll
        for (int j = 0; j < 8; j++) acc[i][j] = 0.f;

    for (int kt = 0; kt < K; kt += 16) {
#pragma unroll
        for (int e = 0; e < 2; e++) {
            int idx = tid + e * 256;
            int row = idx >> 2;
            int kq  = (idx & 3) << 2;
            float4 a = *(const float4*)(A + (size_t)(m0 + row) * K + kt + kq);
            As[kq + 0][row] = a.x; As[kq + 1][row] = a.y;
            As[kq + 2][row] = a.z; As[kq + 3][row] = a.w;
            float4 b = *(const float4*)(Bm + (size_t)(n0 + row) * K + kt + kq);
            Bs[kq + 0][row] = b.x; Bs[kq + 1][row] = b.y;
            Bs[kq + 2][row] = b.z; Bs[kq + 3][row] = b.w;
        }
        __syncthreads();
#pragma unroll
        for (int kk = 0; kk < 16; kk++) {
            float a[8], b[8];
            *(float4*)(a + 0) = *(const float4*)&As[kk][4 * ty];
            *(float4*)(a + 4) = *(const float4*)&As[kk][64 + 4 * ty];
            *(float4*)(b + 0) = *(const float4*)&Bs[kk][4 * tx];
            *(float4*)(b + 4) = *(const float4*)&Bs[kk][64 + 4 * tx];
#pragma unroll
            for (int i = 0; i < 8; i++)
#pragma unroll
                for (int j = 0; j < 8; j++) acc[i][j] += a[i] * b[j];
        }
        __syncthreads();
    }

#pragma unroll
    for (int bi = 0; bi < 2; bi++) {
#pragma unroll
        for (int i = 0; i < 4; i++) {
            int row = m0 + bi * 64 + 4 * ty + i;
#pragma unroll
            for (int bj = 0; bj < 2; bj++) {
                if (EPI == 1) {
                    int col = n0 + bj * 64 + 4 * tx;
                    float4 v;
                    v.x = acc[bi * 4 + i][bj * 4 + 0] + bias[col + 0];
                    v.y = acc[bi * 4 + i][bj * 4 + 1] + bias[col + 1];
                    v.z = acc[bi * 4 + i][bj * 4 + 2] + bias[col + 2];
                    v.w = acc[bi * 4 + i][bj * 4 + 3] + bias[col + 3];
                    *(float4*)(C + (size_t)row * Ncols + col) = v;
                } else {
#pragma unroll
                    for (int j = 0; j < 4; j++) {
                        int col = n0 + bj * 64 + 4 * tx + j;
                        float v = acc[bi * 4 + i][bj * 4 + j] + bias[col];
                        int which = col % 3;
                        int rest  = col / 3;
                        int h = rest >> 6;
                        int d = rest & 63;
                        int bb = row >> 11;
                        int n  = row & 2047;
                        size_t dst;
                        float* out;
                        if (which == 0)      { out = g_Q; dst = (((size_t)(bb * PH + h)) * PN + n) * PD + d; }
                        else if (which == 1) { out = g_K; dst = (((size_t)(bb * PH + h)) * PN + n) * PD + d; }
                        else                 { out = g_V; dst = (((size_t)(bb * PH + h)) * PD + d) * PN + n; }
                        out[dst] = v;
                    }
                }
            }
        }
    }
#endif
}

// ===========================================================================
// Flash attention. TC path: tcgen05 tf32, 128q x 128k tiles, 256 threads.
//   TMEM: S at cols 0..127, O at cols 128..191 (alloc 256).
//   smem (1024-aligned at abase):
//     Q: +0 (2x16K) | K: +32768 (2 stages x 32K) | V: +98304 (2 stages x 32K)
//     Pextra: +163840 (32K). P chunks 0,1 alias current K stage; 2,3 in Pextra.
//   K/V for tile t+1 prefetched during tile t (latency hidden by softmax).
// Fallback: FFMA, two 64-row passes. Both read g_V TRANSPOSED [B,H,D,N].
// ===========================================================================
#define FAO_K 32768
#define FAO_V 98304
#define FAO_P 163840
#define FA_SMEM 201728
#define IDESC_S ((1u << 4) | (2u << 7) | (2u << 10) | ((128u / 8) << 17) | ((128u / 16) << 24))
#define IDESC_O ((1u << 4) | (2u << 7) | (2u << 10) | ((64u / 8) << 17) | ((128u / 16) << 24))

__global__ void __launch_bounds__(256, 1)
flash_attn(const float* __restrict__ Qg, const float* __restrict__ Kg,
           const float* __restrict__ Vtg, float* __restrict__ Og)
{
    extern __shared__ char smem[];
    const int tid = threadIdx.x;
    const int bh = blockIdx.y;
    const size_t baseQK = (size_t)bh * PN * PD;
    const size_t baseVt = (size_t)bh * PD * PN;
    const float scale = 0.125f;

#if HAS_TC
    const uint32_t smem_base = smem_u32(smem);
    const int wid = tid >> 5;
    const int lid = tid & 31;
    const int row = (wid & 3) * 32 + lid;   // query row within tile (= TMEM lane)
    const int colhalf = wid >> 4 >> 0;      // placeholder; real below
    const int ch = wid >> 2;                // 0: S cols 0-63, 1: cols 64-127
    const int n0 = blockIdx.x * 128;

    const uint32_t mbarS = smem_base + 8;
    const uint32_t mbarO = smem_base + 16;
    float* rmax2 = (float*)(smem + 64);         // [2][128]
    float* rsum2 = (float*)(smem + 64 + 1024);  // [2][128]
    const uint32_t abase = (smem_base + 4096 + 1023) & ~1023u;
    char* atl = smem + (abase - smem_base);

    if (wid == 0) {
        TC_ALLOC(smem_base, 256);
        if (elect_one()) { MBAR_INIT(mbarS, 1); MBAR_INIT(mbarO, 1); }
    }
    __syncthreads();
    uint32_t tmem_base;
    asm volatile("ld.shared.b32 %0, [%1];" : "=r"(tmem_base) : "r"(smem_base));

    // KV loader for tile index kt2 into stage s2
    auto load_kv = [&](int kt2, int s2) {
        const int k0n = kt2 * 128;
#pragma unroll
        for (int t = 0; t < 8; t++) {
            int idx = tid + t * 256;
            int r = idx >> 4;           // 0..127 key
            int q = idx & 15;           // 16 float4 per row
            const float* src = Kg + baseQK + (size_t)(k0n + r) * PD + 4 * q;
            uint32_t bo = (uint32_t)(r * 128 + (q & 7) * 16);
            uint32_t sw = bo ^ ((bo >> 3) & 0x70);
            CP_ASYNC16(abase + FAO_K + (uint32_t)s2 * 32768u + (q >> 3) * 16384u + sw, src);
        }
#pragma unroll
        for (int t = 0; t < 8; t++) {
            int idx = tid + t * 256;    // 0..2047
            int d = idx >> 5;           // 0..63
            int qk = idx & 31;          // 32 float4 per row
            const float* src = Vtg + baseVt + (size_t)d * PN + k0n + 4 * qk;
            uint32_t bo = (uint32_t)(d * 128 + (qk & 7) * 16);
            uint32_t sw = bo ^ ((bo >> 3) & 0x70);
            CP_ASYNC16(abase + FAO_V + (uint32_t)s2 * 32768u + (qk >> 3) * 8192u + sw, src);
        }
        CP_COMMIT();
    };

    // Q tile (one group)
#pragma unroll
    for (int t = 0; t < 8; t++) {
        int idx = tid + t * 256;
        int r = idx >> 4;
        int q = idx & 15;
        const float* src = Qg + baseQK + (size_t)(n0 + r) * PD + 4 * q;
        uint32_t bo = (uint32_t)(r * 128 + (q & 7) * 16);
        uint32_t sw = bo ^ ((bo >> 3) & 0x70);
        CP_ASYNC16(abase + (q >> 3) * 16384u + sw, src);
    }
    CP_COMMIT();
    // KV tile 0 into stage 0
    load_kv(0, 0);

    float acc[32];
#pragma unroll
    for (int k = 0; k < 32; k++) acc[k] = 0.f;
    float m_run = -INFINITY, l_run = 0.f;
    int phS = 0, phO = 0;

    for (int kt = 0; kt < PN / 128; kt++) {
        const int s = kt & 1;
        CP_WAIT0();
        __syncthreads();

        // ---- MMA1: S = Q K^T (stage s) ----
        if (wid == 0 && elect_one()) {
            FENCE_PROXY();
            TC_FENCE_AFTER();
#pragma unroll
            for (int c = 0; c < 2; c++) {
                uint64_t qd = make_desc(abase + c * 16384u);
                uint64_t kd = make_desc(abase + FAO_K + (uint32_t)s * 32768u + c * 16384u);
#pragma unroll
                for (int k4 = 0; k4 < 4; k4++)
                    mma_tf32_ss(tmem_base, qd + k4 * 2, kd + k4 * 2, IDESC_S,
                                (c > 0 || k4 > 0) ? 1u : 0u);
            }
            TC_COMMIT(mbarS);
        }
        // ---- prefetch next tile's K/V into the other stage (hidden by softmax)
        if (kt + 1 < PN / 128) load_kv(kt + 1, s ^ 1);

        MBAR_WAIT(mbarS, phS); phS ^= 1;
        TC_FENCE_AFTER();

        // ---- softmax (thread owns half of S row `row`) ----
        uint32_t sr[64];
        TC_LD32X32(sr, tmem_base + 64 * ch);
        TC_LD32X32(sr + 32, tmem_base + 64 * ch + 32);
        TC_WAIT_LD();

        float mloc = -INFINITY;
#pragma unroll
        for (int j = 0; j < 64; j++) mloc = fmaxf(mloc, __uint_as_float(sr[j]));
        mloc *= scale;
        rmax2[ch * 128 + row] = mloc;
        __syncthreads();
        float mnew = fmaxf(m_run, fmaxf(rmax2[row], rmax2[128 + row]));
        float alpha = __expf(m_run - mnew);
        m_run = mnew;

        float lsum = 0.f;
#pragma unroll
        for (int j = 0; j < 64; j++) {
            float p = __expf(__uint_as_float(sr[j]) * scale - mnew);
            lsum += p;
            sr[j] = f2tf32(p);
        }
        rsum2[ch * 128 + row] = lsum;
#pragma unroll
        for (int k = 0; k < 32; k++) acc[k] *= alpha;

        // ---- store P (tf32): keys 64*ch..+63; chunks 0,1 alias K stage s ----
#pragma unroll
        for (int jq = 0; jq < 16; jq++) {
            int key = ch * 64 + jq * 4;
            int chunk = key >> 5;
            uint32_t bo = (uint32_t)(row * 128 + (key & 31) * 4);
            uint32_t sw = bo ^ ((bo >> 3) & 0x70);
            char* base = (chunk < 2)
                ? atl + FAO_K + (uint32_t)s * 32768u + chunk * 16384u
                : atl + FAO_P + (chunk - 2) * 16384u;
            uint4 o;
            o.x = sr[jq * 4 + 0]; o.y = sr[jq * 4 + 1];
            o.z = sr[jq * 4 + 2]; o.w = sr[jq * 4 + 3];
            *(uint4*)(base + sw) = o;
        }
        TC_FENCE_BEFORE();
        __syncthreads();
        l_run = l_run * alpha + rsum2[row] + rsum2[128 + row];

        // ---- MMA2: O = P V^T (fresh each tile, stage s) ----
        if (wid == 0 && elect_one()) {
            FENCE_PROXY();
            TC_FENCE_AFTER();
#pragma unroll
            for (int c = 0; c < 4; c++) {
                uint64_t pd = make_desc((c < 2)
                    ? abase + FAO_K + (uint32_t)s * 32768u + c * 16384u
                    : abase + FAO_P + (c - 2) * 16384u);
                uint64_t vd = make_desc(abase + FAO_V + (uint32_t)s * 32768u + c * 8192u);
#pragma unroll
                for (int k4 = 0; k4 < 4; k4++)
                    mma_tf32_ss(tmem_base + 128, pd + k4 * 2, vd + k4 * 2, IDESC_O,
                                (c > 0 || k4 > 0) ? 1u : 0u);
            }
            TC_COMMIT(mbarO);
        }
        MBAR_WAIT(mbarO, phO); phO ^= 1;
        TC_FENCE_AFTER();

        uint32_t orr[32];
        TC_LD32X32(orr, tmem_base + 128 + 32 * ch);
        TC_WAIT_LD();
#pragma unroll
        for (int k = 0; k < 32; k++) acc[k] += __uint_as_float(orr[k]);
        TC_FENCE_BEFORE();
        __syncthreads();   // all O/P reads done before next tile reuses buffers
    }

    // ---- epilogue (tf32-rounded: feeds proj GEMM) ----
    {
        float invl = 1.f / l_run;
        int b = bh >> 4, h = bh & 15;
        float* dst = g_O + ((size_t)b * PN + n0 + row) * PE + h * 64 + ch * 32;
#pragma unroll
        for (int k = 0; k < 32; k += 4) {
            float4 v;
            v.x = roundtf(acc[k + 0] * invl); v.y = roundtf(acc[k + 1] * invl);
            v.z = roundtf(acc[k + 2] * invl); v.w = roundtf(acc[k + 3] * invl);
            *(float4*)(dst + k) = v;
        }
    }

    __syncthreads();
    if (wid == 0) {
        if (elect_one()) { MBAR_INVAL(mbarS); MBAR_INVAL(mbarO); }
        TC_RELINQ();
        TC_DEALLOC(tmem_base, 256);
    }
    (void)colhalf;
#else
    // ------------------- FFMA fallback (two 64-row passes) -------------------
    float* Qs = (float*)smem;       // 4096 floats
    float* KP = Qs + 64 * 64;       // stride 65
    float* Vs = KP + 64 * 65;       // 4096 floats

    const int tx = tid & 15;
    const int ty = tid >> 4;

    for (int qs = 0; qs < 2; qs++) {
        const int n0 = blockIdx.x * 128 + qs * 64;

        for (int idx = tid; idx < 64 * 64; idx += 256) {
            int r = idx >> 6, d = idx & 63;
            Qs[r * 64 + d] = Qg[baseQK + (size_t)(n0 + r) * PD + d];
        }
        float o[4][4], m_i[4], l_i[4];
#pragma unroll
        for (int i = 0; i < 4; i++) {
            m_i[i] = -INFINITY; l_i[i] = 0.f;
#pragma unroll
            for (int j = 0; j < 4; j++) o[i][j] = 0.f;
        }
        __syncthreads();

        for (int kt = 0; kt < PN / 64; kt++) {
            int k0 = kt * 64;
            for (int idx = tid; idx < 64 * 64; idx += 256) {
                int r = idx >> 6, d = idx & 63;
                KP[r * 65 + d] = Kg[baseQK + (size_t)(k0 + r) * PD + d];
                Vs[r * 64 + d] = Vtg[baseVt + (size_t)d * PN + (k0 + r)];
            }
            __syncthreads();

            float s[4][4];
#pragma unroll
            for (int i = 0; i < 4; i++)
#pragma unroll
                for (int j = 0; j < 4; j++) s[i][j] = 0.f;

            for (int k = 0; k < 64; k += 4) {
                float q[4][4];
#pragma unroll
                for (int i = 0; i < 4; i++) {
                    float4 t = *(const float4*)&Qs[(4 * ty + i) * 64 + k];
                    q[i][0] = t.x; q[i][1] = t.y; q[i][2] = t.z; q[i][3] = t.w;
                }
#pragma unroll
                for (int kk = 0; kk < 4; kk++) {
                    float kv[4];
#pragma unroll
                    for (int j = 0; j < 4; j++)
                        kv[j] = KP[(4 * tx + j) * 65 + k + kk];
#pragma unroll
                    for (int i = 0; i < 4; i++)
#pragma unroll
                        for (int j = 0; j < 4; j++)
                            s[i][j] += q[i][kk] * kv[j];
                }
            }

            float mnew[4], alpha[4];
#pragma unroll
            for (int i = 0; i < 4; i++) {
                float mt = s[i][0];
#pragma unroll
                for (int j = 1; j < 4; j++) mt = fmaxf(mt, s[i][j]);
                mt *= scale;
#pragma unroll
                for (int off = 8; off >= 1; off >>= 1)
                    mt = fmaxf(mt, __shfl_xor_sync(0xffffffffu, mt, off));
                mnew[i] = fmaxf(m_i[i], mt);
                alpha[i] = __expf(m_i[i] - mnew[i]);
                m_i[i] = mnew[i];
            }
            float p[4][4];
#pragma unroll
            for (int i = 0; i < 4; i++) {
                float lt = 0.f;
#pragma unroll
                for (int j = 0; j < 4; j++) {
                    p[i][j] = __expf(s[i][j] * scale - mnew[i]);
                    lt += p[i][j];
                }
#pragma unroll
                for (int off = 8; off >= 1; off >>= 1)
                    lt += __shfl_xor_sync(0xffffffffu, lt, off);
                l_i[i] = l_i[i] * alpha[i] + lt;
#pragma unroll
                for (int j = 0; j < 4; j++) o[i][j] *= alpha[i];
            }

            __syncthreads();
#pragma unroll
            for (int i = 0; i < 4; i++)
#pragma unroll
                for (int j = 0; j < 4; j++)
                    KP[(4 * ty + i) * 65 + 4 * tx + j] = p[i][j];
            __syncthreads();

            for (int jj = 0; jj < 64; jj++) {
                float pv[4];
#pragma unroll
                for (int i = 0; i < 4; i++) pv[i] = KP[(4 * ty + i) * 65 + jj];
                float4 vv = *(const float4*)&Vs[jj * 64 + 4 * tx];
#pragma unroll
                for (int i = 0; i < 4; i++) {
                    o[i][0] += pv[i] * vv.x;
                    o[i][1] += pv[i] * vv.y;
                    o[i][2] += pv[i] * vv.z;
                    o[i][3] += pv[i] * vv.w;
                }
            }
            __syncthreads();
        }

        int b = bh / PH, h = bh % PH;
#pragma unroll
        for (int i = 0; i < 4; i++) {
            float inv_l = 1.f / l_i[i];
            int n = n0 + 4 * ty + i;
            float4 v;
            v.x = o[i][0] * inv_l; v.y = o[i][1] * inv_l;
            v.z = o[i][2] * inv_l; v.w = o[i][3] * inv_l;
            *(float4*)&g_O[((size_t)b * PN + n) * PE + h * 64 + 4 * tx] = v;
        }
        __syncthreads();
    }
#endif
    (void)Og;
}

// ---------------------------------------------------------------------------
extern "C" void kernel_launch(void* const* d_in, const int* in_sizes, int n_in,
                              void* d_out, int out_size)
{
    const float* x      = (const float*)d_in[0];
    const float* w_qkv  = (const float*)d_in[1];
    const float* b_qkv  = (const float*)d_in[2];
    const float* w_proj = (const float*)d_in[3];
    const float* b_proj = (const float*)d_in[4];
    float* out = (float*)d_out;

    cudaFuncSetAttribute(gemm_any<0>,
                         cudaFuncAttributeMaxDynamicSharedMemorySize, GEMM_SMEM);
    cudaFuncSetAttribute(gemm_any<1>,
                         cudaFuncAttributeMaxDynamicSharedMemorySize, GEMM_SMEM);
    cudaFuncSetAttribute(flash_attn,
                         cudaFuncAttributeMaxDynamicSharedMemorySize, FA_SMEM);

    float *xc, *wq, *wp, *Qp, *Kp, *Vp, *Op;
    cudaGetSymbolAddress((void**)&xc, g_xc);
    cudaGetSymbolAddress((void**)&wq, g_wq);
    cudaGetSymbolAddress((void**)&wp, g_wp);
    cudaGetSymbolAddress((void**)&Qp, g_Q);
    cudaGetSymbolAddress((void**)&Kp, g_K);
    cudaGetSymbolAddress((void**)&Vp, g_V);
    cudaGetSymbolAddress((void**)&Op, g_O);

    // 0) Pre-round inputs to tf32
    prep_convert<<<1024, 256>>>(x, w_qkv, w_proj);

    // 1) QKV projection + scatter (V stored transposed)
    {
        dim3 grid(QKV_COLS / 128, M_TOK / 128);
        gemm_any<0><<<grid, 256, GEMM_SMEM>>>(xc, wq, b_qkv, nullptr,
                                              QKV_COLS, PE);
    }

    // 2) Flash attention
    {
        dim3 grid(PN / 128, PB * PH);
        flash_attn<<<grid, 256, FA_SMEM>>>(Qp, Kp, Vp, Op);
    }

    // 3) Output projection
    {
        dim3 grid(PE / 128, M_TOK / 128);
        gemm_any<1><<<grid, 256, GEMM_SMEM>>>(Op, wp, b_proj, out,
                                              PE, PE);
    }
}

// round 15
// speedup vs baseline: 5.8261x; 1.1065x over previous
#include <cuda_runtime.h>
#include <math.h>
#include <stdint.h>

// Problem constants
#define PB 2
#define PN 2048
#define PE 1024
#define PH 16
#define PD 64
#define M_TOK (PB * PN)        // 4096 tokens
#define QKV_COLS (3 * PE)      // 3072

// Does this compilation pass support tcgen05 (arch-specific sm_10xa target)?
#if defined(__CUDA_ARCH_FEAT_SM103_ALL) || defined(__CUDA_ARCH_FEAT_SM101_ALL) || defined(__CUDA_ARCH_FEAT_SM100_ALL)
#define HAS_TC 1
#else
#define HAS_TC 0
#endif

// Scratch (no cudaMalloc allowed)
__device__ float g_Q[PB * PH * PN * PD];   // [B,H,N,D] (tf32-rounded)
__device__ float g_K[PB * PH * PN * PD];   // [B,H,N,D] (tf32-rounded)
__device__ float g_V[PB * PH * PN * PD];   // [B,H,D,N] TRANSPOSED (tf32-rounded)
__device__ float g_O[M_TOK * PE];          // [B,N,E] pre-projection (tf32-rounded)
__device__ float g_xc[M_TOK * PE];         // x, tf32-rounded
__device__ float g_wq[QKV_COLS * PE];      // w_qkv, tf32-rounded
__device__ float g_wp[PE * PE];            // w_proj, tf32-rounded

// ===========================================================================
// PTX helpers
// ===========================================================================
__device__ __forceinline__ uint32_t smem_u32(const void* p) {
    uint32_t a;
    asm("{ .reg .u64 t; cvta.to.shared.u64 t, %1; cvt.u32.u64 %0, t; }"
        : "=r"(a) : "l"(p));
    return a;
}
__device__ __forceinline__ uint32_t f2tf32(float f) {
    uint32_t r;
    asm("cvt.rna.tf32.f32 %0, %1;" : "=r"(r) : "f"(f));
    return r;
}
__device__ __forceinline__ float roundtf(float f) {
    return __uint_as_float(f2tf32(f));
}
#define CP_ASYNC16(dst, src) asm volatile("cp.async.ca.shared.global [%0], [%1], 16;" :: "r"((uint32_t)(dst)), "l"(src) : "memory")
#define CP_COMMIT()          asm volatile("cp.async.commit_group;" ::: "memory")
#define CP_WAIT(n)           asm volatile("cp.async.wait_group %0;" :: "n"(n) : "memory")

#if HAS_TC
__device__ __forceinline__ uint32_t elect_one() {
    uint32_t pred;
    asm volatile("{\n\t.reg .pred p;\n\telect.sync _|p, 0xFFFFFFFF;\n\t"
                 "selp.b32 %0, 1, 0, p;\n\t}" : "=r"(pred));
    return pred;
}
#define TC_ALLOC(sm, n)  asm volatile("tcgen05.alloc.cta_group::1.sync.aligned.shared::cta.b32 [%0], %1;" :: "r"((uint32_t)(sm)), "r"((uint32_t)(n)) : "memory")
#define TC_DEALLOC(t, n) asm volatile("tcgen05.dealloc.cta_group::1.sync.aligned.b32 %0, %1;" :: "r"(t), "r"((uint32_t)(n)))
#define TC_RELINQ()      asm volatile("tcgen05.relinquish_alloc_permit.cta_group::1.sync.aligned;")
#define TC_COMMIT(mb)    asm volatile("tcgen05.commit.cta_group::1.mbarrier::arrive::one.shared::cluster.b64 [%0];" :: "r"((uint32_t)(mb)) : "memory")
#define TC_FENCE_AFTER() asm volatile("tcgen05.fence::after_thread_sync;" ::: "memory")
#define TC_FENCE_BEFORE() asm volatile("tcgen05.fence::before_thread_sync;" ::: "memory")
#define TC_WAIT_LD()     asm volatile("tcgen05.wait::ld.sync.aligned;" ::: "memory")
#define FENCE_PROXY()    asm volatile("fence.proxy.async.shared::cta;" ::: "memory")
#define MBAR_INIT(mb, c) asm volatile("mbarrier.init.shared.b64 [%0], %1;" :: "r"((uint32_t)(mb)), "r"((uint32_t)(c)) : "memory")
#define MBAR_INVAL(mb)   asm volatile("mbarrier.inval.shared.b64 [%0];" :: "r"((uint32_t)(mb)) : "memory")

#define MBAR_WAIT(mb, ph) do {                                             \
    uint32_t _m = (uint32_t)(mb); uint32_t _p = (uint32_t)(ph); uint32_t _d;\
    asm volatile("{\n\t.reg .pred p;\n\t"                                  \
        "mbarrier.try_wait.parity.acquire.cta.shared::cta.b64 p, [%1], %2;\n\t" \
        "selp.b32 %0, 1, 0, p;\n\t}" : "=r"(_d) : "r"(_m), "r"(_p) : "memory"); \
    if (!_d) {                                                             \
        asm volatile("{\n\t.reg .pred P1;\n\t"                             \
            "WL_%=:\n\t"                                                   \
            "mbarrier.try_wait.parity.acquire.cta.shared::cta.b64 P1, [%0], %1, 0x989680;\n\t" \
            "@P1 bra.uni WD_%=;\n\t"                                       \
            "bra.uni WL_%=;\n\t"                                           \
            "WD_%=:\n\t}" :: "r"(_m), "r"(_p) : "memory");                 \
    }                                                                      \
} while (0)

#define TC_LD32X32(r, ta)                                                  \
    asm volatile("tcgen05.ld.sync.aligned.32x32b.x32.b32 "                 \
        "{%0, %1, %2, %3, %4, %5, %6, %7, "                                \
        " %8, %9, %10, %11, %12, %13, %14, %15, "                          \
        " %16, %17, %18, %19, %20, %21, %22, %23, "                        \
        " %24, %25, %26, %27, %28, %29, %30, %31}, [%32];"                 \
        : "=r"((r)[0]),  "=r"((r)[1]),  "=r"((r)[2]),  "=r"((r)[3]),       \
          "=r"((r)[4]),  "=r"((r)[5]),  "=r"((r)[6]),  "=r"((r)[7]),       \
          "=r"((r)[8]),  "=r"((r)[9]),  "=r"((r)[10]), "=r"((r)[11]),      \
          "=r"((r)[12]), "=r"((r)[13]), "=r"((r)[14]), "=r"((r)[15]),      \
          "=r"((r)[16]), "=r"((r)[17]), "=r"((r)[18]), "=r"((r)[19]),      \
          "=r"((r)[20]), "=r"((r)[21]), "=r"((r)[22]), "=r"((r)[23]),      \
          "=r"((r)[24]), "=r"((r)[25]), "=r"((r)[26]), "=r"((r)[27]),      \
          "=r"((r)[28]), "=r"((r)[29]), "=r"((r)[30]), "=r"((r)[31])       \
        : "r"(ta))

// SW128 K-major smem descriptor: layout=2, version=1, SBO=64, LBO=1
__device__ __forceinline__ uint64_t make_desc(uint32_t base) {
    uint64_t d = (uint64_t)2 << 61 | (uint64_t)1 << 46 |
                 (uint64_t)64 << 32 | (uint64_t)1 << 16;
    return d | ((uint64_t)(base >> 4) & 0x3FFF);
}

__device__ __forceinline__ void mma_tf32_ss(uint32_t d, uint64_t ad, uint64_t bd,
                                            uint32_t idesc, uint32_t en) {
    asm volatile("{\n\t.reg .pred p;\n\tsetp.ne.u32 p, %5, 0;\n\t"
                 "tcgen05.mma.cta_group::1.kind::tf32 [%0], %1, %2, %3, "
                 "{%4, %4, %4, %4}, p;\n\t}"
                 :: "r"(d), "l"(ad), "l"(bd), "r"(idesc), "r"(0u), "r"(en)
                 : "memory");
}
#endif  // HAS_TC

// ===========================================================================
// Prep: round inputs to tf32 once
// ===========================================================================
__global__ void prep_convert(const float* __restrict__ x,
                             const float* __restrict__ wq,
                             const float* __restrict__ wp)
{
    const int g = blockIdx.x * blockDim.x + threadIdx.x;
    const int stride = gridDim.x * blockDim.x;
    const int n1 = M_TOK * PE / 4;
    const int n2 = QKV_COLS * PE / 4;
    const int n3 = PE * PE / 4;
    for (int i = g; i < n1; i += stride) {
        float4 v = ((const float4*)x)[i];
        v.x = roundtf(v.x); v.y = roundtf(v.y);
        v.z = roundtf(v.z); v.w = roundtf(v.w);
        ((float4*)g_xc)[i] = v;
    }
    for (int i = g; i < n2; i += stride) {
        float4 v = ((const float4*)wq)[i];
        v.x = roundtf(v.x); v.y = roundtf(v.y);
        v.z = roundtf(v.z); v.w = roundtf(v.w);
        ((float4*)g_wq)[i] = v;
    }
    for (int i = g; i < n3; i += stride) {
        float4 v = ((const float4*)wp)[i];
        v.x = roundtf(v.x); v.y = roundtf(v.y);
        v.z = roundtf(v.z); v.w = roundtf(v.w);
        ((float4*)g_wp)[i] = v;
    }
}

// ===========================================================================
// GEMM-NT: C[M,Ncols] = A[M,K] * Bm[Ncols,K]^T (+bias). Operands pre-rounded.
// 128x128 tile per CTA, 256 threads, grid (Ncols/128, M/128).
// TC path: 5-stage pipelined cp.async -> tcgen05 tf32 SS MMA.
//   Stage reuse rule: load(c+4) waits MMA(c-1) (same stage, (c-1)%5).
//   Steady-state cp wait: wait_group 3 (4 groups in flight).
// EPI 0: scatter into g_Q/g_K (N,D) + g_V (D,N) with bias, tf32-rounded.
// EPI 1: plain store + bias.
// ===========================================================================
#define IDESC_TF32 ((1u << 4) | (2u << 7) | (2u << 10) | ((128u / 8) << 17) | ((128u / 16) << 24))
#define NSTAGE 5
#define GEMM_SMEM 166912

template <int EPI>
__global__ void __launch_bounds__(256, 1) __cluster_dims__(1, 1, 1)
gemm_any(const float* __restrict__ A, const float* __restrict__ Bm,
         const float* __restrict__ bias, float* __restrict__ C,
         int Ncols, int K)
{
    extern __shared__ char smem[];
    const int tid = threadIdx.x;
    const int m0 = blockIdx.y * 128;
    const int n0 = blockIdx.x * 128;

#if HAS_TC
    const uint32_t smem_base = smem_u32(smem);
    const int wid = tid >> 5;
    const int lid = tid & 31;
    const uint32_t abase = (smem_base + 64 + 1023) & ~1023u;

    if (wid == 0) {
        TC_ALLOC(smem_base, 128);
        if (elect_one()) {
#pragma unroll
            for (int i = 0; i < NSTAGE; i++) MBAR_INIT(smem_base + 8 + 8 * i, 1);
        }
    }
    __syncthreads();
    uint32_t tmem_base;
    asm volatile("ld.shared.b32 %0, [%1];" : "=r"(tmem_base) : "r"(smem_base));

    const int nchunks = K / 32;          // 32 here (K=1024), >= NSTAGE
    uint32_t ph_bits = 0;

    // issue loads for chunk `c` into stage `st`
    auto issue_load = [&](int c, int st) {
        const uint32_t stage = abase + (uint32_t)st * 32768u;
        const int kt = c * 32;
#pragma unroll
        for (int t = 0; t < 8; t++) {
            int idx = tid + t * 256;            // 0..2047 float4 slots
            int isB = idx >> 10;
            int r = (idx & 1023) >> 3;
            int q = idx & 7;
            const float* src = (isB ? Bm + (size_t)(n0 + r) * K
                                    : A + (size_t)(m0 + r) * K) + kt + 4 * q;
            uint32_t bo = (uint32_t)(r * 128 + q * 16);
            uint32_t sw = bo ^ ((bo >> 3) & 0x70);
            CP_ASYNC16(stage + (isB ? 16384u : 0u) + sw, src);
        }
        CP_COMMIT();
    };

    // prologue: chunks 0..3 into stages 0..3
    issue_load(0, 0);
    issue_load(1, 1);
    issue_load(2, 2);
    issue_load(3, 3);

    for (int c = 0; c < nchunks; c++) {
        const int st = c % NSTAGE;
        // wait until chunk c's group is complete (keep the rest in flight)
        {
            int pending = nchunks - 1 - c;          // groups issued beyond c
            if (pending > 3) pending = 3;
            if (pending == 3)      CP_WAIT(3);
            else if (pending == 2) CP_WAIT(2);
            else if (pending == 1) CP_WAIT(1);
            else                   CP_WAIT(0);
        }
        __syncthreads();
        if (wid == 0 && elect_one()) {
            FENCE_PROXY();
            uint64_t ad = make_desc(abase + (uint32_t)st * 32768u);
            uint64_t bd = make_desc(abase + (uint32_t)st * 32768u + 16384u);
#pragma unroll
            for (int k4 = 0; k4 < 4; k4++)
                mma_tf32_ss(tmem_base, ad + k4 * 2, bd + k4 * 2, IDESC_TF32,
                            (c > 0 || k4 > 0) ? 1u : 0u);
            TC_COMMIT(smem_base + 8 + 8 * st);
        }
        const int nx = c + NSTAGE - 1;              // next chunk to load
        if (nx < nchunks) {
            const int nst = nx % NSTAGE;            // == (c-1)%NSTAGE for c>=1
            if (c >= 1) {
                MBAR_WAIT(smem_base + 8 + 8 * nst, (ph_bits >> nst) & 1);
                ph_bits ^= (1u << nst);
            }
            issue_load(nx, nst);
        }
    }
    // tail: drain all stages' MMA groups
#pragma unroll
    for (int i = 0; i < NSTAGE; i++)
        MBAR_WAIT(smem_base + 8 + 8 * i, (ph_bits >> i) & 1);
    TC_FENCE_AFTER();

    float* eps = (float*)(smem + (abase - smem_base));
    const int ESTRIDE = 132;
    if (wid < 4) {
#pragma unroll
        for (int base = 0; base < 128; base += 32) {
            uint32_t r[32];
            TC_LD32X32(r, tmem_base + base);
            TC_WAIT_LD();
#pragma unroll
            for (int cc = 0; cc < 32; cc++)
                eps[(wid * 32 + lid) * ESTRIDE + base + cc] = __uint_as_float(r[cc]);
        }
        TC_FENCE_BEFORE();
    }
    __syncthreads();

    if (EPI == 1) {
        for (int idx = tid; idx < 128 * 32; idx += 256) {
            int row = idx >> 5, q = idx & 31;
            float4 v = *(const float4*)&eps[row * ESTRIDE + 4 * q];
            int colg = n0 + 4 * q;
            v.x += bias[colg + 0]; v.y += bias[colg + 1];
            v.z += bias[colg + 2]; v.w += bias[colg + 3];
            *(float4*)(C + (size_t)(m0 + row) * Ncols + colg) = v;
        }
    } else {
        // Q/K scatter (d-contiguous), tf32-rounded
        for (int idx = tid; idx < 128 * 128; idx += 256) {
            int row = idx >> 7, col = idx & 127;
            int colg = n0 + col;
            int which = colg % 3;
            if (which == 2) continue;    // V handled below
            float v = eps[row * ESTRIDE + col] + bias[colg];
            int rest = colg / 3;         // h*64 + d
            int h = rest >> 6;
            int d = rest & 63;
            int tok = m0 + row;
            int bb = tok >> 11;
            int n = tok & 2047;
            float* out = (which == 0) ? g_Q : g_K;
            out[(((size_t)(bb * PH + h)) * PN + n) * PD + d] = roundtf(v);
        }
        // V scatter: coalesced along n (one col per warp, lanes sweep rows)
        {
            int bb = m0 >> 11;
            int nbase = m0 & 2047;
            int c0 = ((2 - (n0 % 3)) % 3 + 3) % 3;   // first col with which==2
            for (int j = wid; c0 + 3 * j < 128; j += 8) {
                int col = c0 + 3 * j;
                int colg = n0 + col;
                int rest = colg / 3;
                int h = rest >> 6;
                int d = rest & 63;
                float bv = bias[colg];
                float* dstp = g_V + (((size_t)(bb * PH + h)) * PD + d) * PN + nbase;
                for (int r = lid; r < 128; r += 32)
                    dstp[r] = roundtf(eps[r * ESTRIDE + col] + bv);
            }
        }
    }

    __syncthreads();
    if (wid == 0) {
        if (elect_one()) {
#pragma unroll
            for (int i = 0; i < NSTAGE; i++) MBAR_INVAL(smem_base + 8 + 8 * i);
        }
        TC_RELINQ();
        TC_DEALLOC(tmem_base, 128);
    }
#else
    // ------------------------- FFMA fallback path -------------------------
    float (*As)[132] = reinterpret_cast<float(*)[132]>(smem);
    float (*Bs)[132] = reinterpret_cast<float(*)[132]>(smem + 16 * 132 * sizeof(float));

    const int tx = tid & 15;
    const int ty = tid >> 4;

    float acc[8][8];
#pragma unroll
    for (int i = 0; i < 8; i++)
#pragma unroll
        for (int j = 0; j < 8; j++) acc[i][j] = 0.f;

    for (int kt = 0; kt < K; kt += 16) {
#pragma unroll
        for (int e = 0; e < 2; e++) {
            int idx = tid + e * 256;
            int row = idx >> 2;
            int kq  = (idx & 3) << 2;
            float4 a = *(const float4*)(A + (size_t)(m0 + row) * K + kt + kq);
            As[kq + 0][row] = a.x; As[kq + 1][row] = a.y;
            As[kq + 2][row] = a.z; As[kq + 3][row] = a.w;
            float4 b = *(const float4*)(Bm + (size_t)(n0 + row) * K + kt + kq);
            Bs[kq + 0][row] = b.x; Bs[kq + 1][row] = b.y;
            Bs[kq + 2][row] = b.z; Bs[kq + 3][row] = b.w;
        }
        __syncthreads();
#pragma unroll
        for (int kk = 0; kk < 16; kk++) {
            float a[8], b[8];
            *(float4*)(a + 0) = *(const float4*)&As[kk][4 * ty];
            *(float4*)(a + 4) = *(const float4*)&As[kk][64 + 4 * ty];
            *(float4*)(b + 0) = *(const float4*)&Bs[kk][4 * tx];
            *(float4*)(b + 4) = *(const float4*)&Bs[kk][64 + 4 * tx];
#pragma unroll
            for (int i = 0; i < 8; i++)
#pragma unroll
                for (int j = 0; j < 8; j++) acc[i][j] += a[i] * b[j];
        }
        __syncthreads();
    }

#pragma unroll
    for (int bi = 0; bi < 2; bi++) {
#pragma unroll
        for (int i = 0; i < 4; i++) {
            int row = m0 + bi * 64 + 4 * ty + i;
#pragma unroll
            for (int bj = 0; bj < 2; bj++) {
                if (EPI == 1) {
                    int col = n0 + bj * 64 + 4 * tx;
                    float4 v;
                    v.x = acc[bi * 4 + i][bj * 4 + 0] + bias[col + 0];
                    v.y = acc[bi * 4 + i][bj * 4 + 1] + bias[col + 1];
                    v.z = acc[bi * 4 + i][bj * 4 + 2] + bias[col + 2];
                    v.w = acc[bi * 4 + i][bj * 4 + 3] + bias[col + 3];
                    *(float4*)(C + (size_t)row * Ncols + col) = v;
                } else {
#pragma unroll
                    for (int j = 0; j < 4; j++) {
                        int col = n0 + bj * 64 + 4 * tx + j;
                        float v = acc[bi * 4 + i][bj * 4 + j] + bias[col];
                        int which = col % 3;
                        int rest  = col / 3;
                        int h = rest >> 6;
                        int d = rest & 63;
                        int bb = row >> 11;
                        int n  = row & 2047;
                        size_t dst;
                        float* out;
                        if (which == 0)      { out = g_Q; dst = (((size_t)(bb * PH + h)) * PN + n) * PD + d; }
                        else if (which == 1) { out = g_K; dst = (((size_t)(bb * PH + h)) * PN + n) * PD + d; }
                        else                 { out = g_V; dst = (((size_t)(bb * PH + h)) * PD + d) * PN + n; }
                        out[dst] = v;
                    }
                }
            }
        }
    }
#endif
}

// ===========================================================================
// Flash attention. TC path: tcgen05 tf32, 128q x 128k tiles, 256 threads.
//   TMEM: S at cols 0..127, O at cols 128..191 (alloc 256).
//   smem (1024-aligned at abase):
//     Q: +0 (2x16K) | K: +32768 (2 stages x 32K) | V: +98304 (2 stages x 32K)
//     Pextra: +163840 (32K). P chunks 0,1 alias current K stage; 2,3 in Pextra.
//   K/V for tile t+1 prefetched during tile t (latency hidden by softmax).
// Fallback: FFMA, two 64-row passes. Both read g_V TRANSPOSED [B,H,D,N].
// ===========================================================================
#define FAO_K 32768
#define FAO_V 98304
#define FAO_P 163840
#define FA_SMEM 201728
#define IDESC_S ((1u << 4) | (2u << 7) | (2u << 10) | ((128u / 8) << 17) | ((128u / 16) << 24))
#define IDESC_O ((1u << 4) | (2u << 7) | (2u << 10) | ((64u / 8) << 17) | ((128u / 16) << 24))

__global__ void __launch_bounds__(256, 1)
flash_attn(const float* __restrict__ Qg, const float* __restrict__ Kg,
           const float* __restrict__ Vtg, float* __restrict__ Og)
{
    extern __shared__ char smem[];
    const int tid = threadIdx.x;
    const int bh = blockIdx.y;
    const size_t baseQK = (size_t)bh * PN * PD;
    const size_t baseVt = (size_t)bh * PD * PN;
    const float scale = 0.125f;

#if HAS_TC
    const uint32_t smem_base = smem_u32(smem);
    const int wid = tid >> 5;
    const int lid = tid & 31;
    const int row = (wid & 3) * 32 + lid;   // query row within tile (= TMEM lane)
    const int ch = wid >> 2;                // 0: S cols 0-63, 1: cols 64-127
    const int n0 = blockIdx.x * 128;

    const uint32_t mbarS = smem_base + 8;
    const uint32_t mbarO = smem_base + 16;
    float* rmax2 = (float*)(smem + 64);         // [2][128]
    float* rsum2 = (float*)(smem + 64 + 1024);  // [2][128]
    const uint32_t abase = (smem_base + 4096 + 1023) & ~1023u;
    char* atl = smem + (abase - smem_base);

    if (wid == 0) {
        TC_ALLOC(smem_base, 256);
        if (elect_one()) { MBAR_INIT(mbarS, 1); MBAR_INIT(mbarO, 1); }
    }
    __syncthreads();
    uint32_t tmem_base;
    asm volatile("ld.shared.b32 %0, [%1];" : "=r"(tmem_base) : "r"(smem_base));

    // KV loader for tile index kt2 into stage s2
    auto load_kv = [&](int kt2, int s2) {
        const int k0n = kt2 * 128;
#pragma unroll
        for (int t = 0; t < 8; t++) {
            int idx = tid + t * 256;
            int r = idx >> 4;           // 0..127 key
            int q = idx & 15;           // 16 float4 per row
            const float* src = Kg + baseQK + (size_t)(k0n + r) * PD + 4 * q;
            uint32_t bo = (uint32_t)(r * 128 + (q & 7) * 16);
            uint32_t sw = bo ^ ((bo >> 3) & 0x70);
            CP_ASYNC16(abase + FAO_K + (uint32_t)s2 * 32768u + (q >> 3) * 16384u + sw, src);
        }
#pragma unroll
        for (int t = 0; t < 8; t++) {
            int idx = tid + t * 256;    // 0..2047
            int d = idx >> 5;           // 0..63
            int qk = idx & 31;          // 32 float4 per row
            const float* src = Vtg + baseVt + (size_t)d * PN + k0n + 4 * qk;
            uint32_t bo = (uint32_t)(d * 128 + (qk & 7) * 16);
            uint32_t sw = bo ^ ((bo >> 3) & 0x70);
            CP_ASYNC16(abase + FAO_V + (uint32_t)s2 * 32768u + (qk >> 3) * 8192u + sw, src);
        }
        CP_COMMIT();
    };

    // Q tile (one group)
#pragma unroll
    for (int t = 0; t < 8; t++) {
        int idx = tid + t * 256;
        int r = idx >> 4;
        int q = idx & 15;
        const float* src = Qg + baseQK + (size_t)(n0 + r) * PD + 4 * q;
        uint32_t bo = (uint32_t)(r * 128 + (q & 7) * 16);
        uint32_t sw = bo ^ ((bo >> 3) & 0x70);
        CP_ASYNC16(abase + (q >> 3) * 16384u + sw, src);
    }
    CP_COMMIT();
    // KV tile 0 into stage 0
    load_kv(0, 0);

    float acc[32];
#pragma unroll
    for (int k = 0; k < 32; k++) acc[k] = 0.f;
    float m_run = -INFINITY, l_run = 0.f;
    int phS = 0, phO = 0;

    for (int kt = 0; kt < PN / 128; kt++) {
        const int s = kt & 1;
        CP_WAIT(0);
        __syncthreads();

        // ---- MMA1: S = Q K^T (stage s) ----
        if (wid == 0 && elect_one()) {
            FENCE_PROXY();
            TC_FENCE_AFTER();
#pragma unroll
            for (int c = 0; c < 2; c++) {
                uint64_t qd = make_desc(abase + c * 16384u);
                uint64_t kd = make_desc(abase + FAO_K + (uint32_t)s * 32768u + c * 16384u);
#pragma unroll
                for (int k4 = 0; k4 < 4; k4++)
                    mma_tf32_ss(tmem_base, qd + k4 * 2, kd + k4 * 2, IDESC_S,
                                (c > 0 || k4 > 0) ? 1u : 0u);
            }
            TC_COMMIT(mbarS);
        }
        // ---- prefetch next tile's K/V into the other stage (hidden by softmax)
        if (kt + 1 < PN / 128) load_kv(kt + 1, s ^ 1);

        MBAR_WAIT(mbarS, phS); phS ^= 1;
        TC_FENCE_AFTER();

        // ---- softmax (thread owns half of S row `row`) ----
        uint32_t sr[64];
        TC_LD32X32(sr, tmem_base + 64 * ch);
        TC_LD32X32(sr + 32, tmem_base + 64 * ch + 32);
        TC_WAIT_LD();

        float mloc = -INFINITY;
#pragma unroll
        for (int j = 0; j < 64; j++) mloc = fmaxf(mloc, __uint_as_float(sr[j]));
        mloc *= scale;
        rmax2[ch * 128 + row] = mloc;
        __syncthreads();
        float mnew = fmaxf(m_run, fmaxf(rmax2[row], rmax2[128 + row]));
        float alpha = __expf(m_run - mnew);
        m_run = mnew;

        float lsum = 0.f;
#pragma unroll
        for (int j = 0; j < 64; j++) {
            float p = __expf(__uint_as_float(sr[j]) * scale - mnew);
            lsum += p;
            sr[j] = f2tf32(p);
        }
        rsum2[ch * 128 + row] = lsum;
#pragma unroll
        for (int k = 0; k < 32; k++) acc[k] *= alpha;

        // ---- store P (tf32): keys 64*ch..+63; chunks 0,1 alias K stage s ----
#pragma unroll
        for (int jq = 0; jq < 16; jq++) {
            int key = ch * 64 + jq * 4;
            int chunk = key >> 5;
            uint32_t bo = (uint32_t)(row * 128 + (key & 31) * 4);
            uint32_t sw = bo ^ ((bo >> 3) & 0x70);
            char* base = (chunk < 2)
                ? atl + FAO_K + (uint32_t)s * 32768u + chunk * 16384u
                : atl + FAO_P + (chunk - 2) * 16384u;
            uint4 o;
            o.x = sr[jq * 4 + 0]; o.y = sr[jq * 4 + 1];
            o.z = sr[jq * 4 + 2]; o.w = sr[jq * 4 + 3];
            *(uint4*)(base + sw) = o;
        }
        TC_FENCE_BEFORE();
        __syncthreads();
        l_run = l_run * alpha + rsum2[row] + rsum2[128 + row];

        // ---- MMA2: O = P V^T (fresh each tile, stage s) ----
        if (wid == 0 && elect_one()) {
            FENCE_PROXY();
            TC_FENCE_AFTER();
#pragma unroll
            for (int c = 0; c < 4; c++) {
                uint64_t pd = make_desc((c < 2)
                    ? abase + FAO_K + (uint32_t)s * 32768u + c * 16384u
                    : abase + FAO_P + (c - 2) * 16384u);
                uint64_t vd = make_desc(abase + FAO_V + (uint32_t)s * 32768u + c * 8192u);
#pragma unroll
                for (int k4 = 0; k4 < 4; k4++)
                    mma_tf32_ss(tmem_base + 128, pd + k4 * 2, vd + k4 * 2, IDESC_O,
                                (c > 0 || k4 > 0) ? 1u : 0u);
            }
            TC_COMMIT(mbarO);
        }
        MBAR_WAIT(mbarO, phO); phO ^= 1;
        TC_FENCE_AFTER();

        uint32_t orr[32];
        TC_LD32X32(orr, tmem_base + 128 + 32 * ch);
        TC_WAIT_LD();
#pragma unroll
        for (int k = 0; k < 32; k++) acc[k] += __uint_as_float(orr[k]);
        TC_FENCE_BEFORE();
        __syncthreads();   // all O/P reads done before next tile reuses buffers
    }

    // ---- epilogue (tf32-rounded: feeds proj GEMM) ----
    {
        float invl = 1.f / l_run;
        int b = bh >> 4, h = bh & 15;
        float* dst = g_O + ((size_t)b * PN + n0 + row) * PE + h * 64 + ch * 32;
#pragma unroll
        for (int k = 0; k < 32; k += 4) {
            float4 v;
            v.x = roundtf(acc[k + 0] * invl); v.y = roundtf(acc[k + 1] * invl);
            v.z = roundtf(acc[k + 2] * invl); v.w = roundtf(acc[k + 3] * invl);
            *(float4*)(dst + k) = v;
        }
    }

    __syncthreads();
    if (wid == 0) {
        if (elect_one()) { MBAR_INVAL(mbarS); MBAR_INVAL(mbarO); }
        TC_RELINQ();
        TC_DEALLOC(tmem_base, 256);
    }
#else
    // ------------------- FFMA fallback (two 64-row passes) -------------------
    float* Qs = (float*)smem;       // 4096 floats
    float* KP = Qs + 64 * 64;       // stride 65
    float* Vs = KP + 64 * 65;       // 4096 floats

    const int tx = tid & 15;
    const int ty = tid >> 4;

    for (int qs = 0; qs < 2; qs++) {
        const int n0 = blockIdx.x * 128 + qs * 64;

        for (int idx = tid; idx < 64 * 64; idx += 256) {
            int r = idx >> 6, d = idx & 63;
            Qs[r * 64 + d] = Qg[baseQK + (size_t)(n0 + r) * PD + d];
        }
        float o[4][4], m_i[4], l_i[4];
#pragma unroll
        for (int i = 0; i < 4; i++) {
            m_i[i] = -INFINITY; l_i[i] = 0.f;
#pragma unroll
            for (int j = 0; j < 4; j++) o[i][j] = 0.f;
        }
        __syncthreads();

        for (int kt = 0; kt < PN / 64; kt++) {
            int k0 = kt * 64;
            for (int idx = tid; idx < 64 * 64; idx += 256) {
                int r = idx >> 6, d = idx & 63;
                KP[r * 65 + d] = Kg[baseQK + (size_t)(k0 + r) * PD + d];
                Vs[r * 64 + d] = Vtg[baseVt + (size_t)d * PN + (k0 + r)];
            }
            __syncthreads();

            float s[4][4];
#pragma unroll
            for (int i = 0; i < 4; i++)
#pragma unroll
                for (int j = 0; j < 4; j++) s[i][j] = 0.f;

            for (int k = 0; k < 64; k += 4) {
                float q[4][4];
#pragma unroll
                for (int i = 0; i < 4; i++) {
                    float4 t = *(const float4*)&Qs[(4 * ty + i) * 64 + k];
                    q[i][0] = t.x; q[i][1] = t.y; q[i][2] = t.z; q[i][3] = t.w;
                }
#pragma unroll
                for (int kk = 0; kk < 4; kk++) {
                    float kv[4];
#pragma unroll
                    for (int j = 0; j < 4; j++)
                        kv[j] = KP[(4 * tx + j) * 65 + k + kk];
#pragma unroll
                    for (int i = 0; i < 4; i++)
#pragma unroll
                        for (int j = 0; j < 4; j++)
                            s[i][j] += q[i][kk] * kv[j];
                }
            }

            float mnew[4], alpha[4];
#pragma unroll
            for (int i = 0; i < 4; i++) {
                float mt = s[i][0];
#pragma unroll
                for (int j = 1; j < 4; j++) mt = fmaxf(mt, s[i][j]);
                mt *= scale;
#pragma unroll
                for (int off = 8; off >= 1; off >>= 1)
                    mt = fmaxf(mt, __shfl_xor_sync(0xffffffffu, mt, off));
                mnew[i] = fmaxf(m_i[i], mt);
                alpha[i] = __expf(m_i[i] - mnew[i]);
                m_i[i] = mnew[i];
            }
            float p[4][4];
#pragma unroll
            for (int i = 0; i < 4; i++) {
                float lt = 0.f;
#pragma unroll
                for (int j = 0; j < 4; j++) {
                    p[i][j] = __expf(s[i][j] * scale - mnew[i]);
                    lt += p[i][j];
                }
#pragma unroll
                for (int off = 8; off >= 1; off >>= 1)
                    lt += __shfl_xor_sync(0xffffffffu, lt, off);
                l_i[i] = l_i[i] * alpha[i] + lt;
#pragma unroll
                for (int j = 0; j < 4; j++) o[i][j] *= alpha[i];
            }

            __syncthreads();
#pragma unroll
            for (int i = 0; i < 4; i++)
#pragma unroll
                for (int j = 0; j < 4; j++)
                    KP[(4 * ty + i) * 65 + 4 * tx + j] = p[i][j];
            __syncthreads();

            for (int jj = 0; jj < 64; jj++) {
                float pv[4];
#pragma unroll
                for (int i = 0; i < 4; i++) pv[i] = KP[(4 * ty + i) * 65 + jj];
                float4 vv = *(const float4*)&Vs[jj * 64 + 4 * tx];
#pragma unroll
                for (int i = 0; i < 4; i++) {
                    o[i][0] += pv[i] * vv.x;
                    o[i][1] += pv[i] * vv.y;
                    o[i][2] += pv[i] * vv.z;
                    o[i][3] += pv[i] * vv.w;
                }
            }
            __syncthreads();
        }

        int b = bh / PH, h = bh % PH;
#pragma unroll
        for (int i = 0; i < 4; i++) {
            float inv_l = 1.f / l_i[i];
            int n = n0 + 4 * ty + i;
            float4 v;
            v.x = o[i][0] * inv_l; v.y = o[i][1] * inv_l;
            v.z = o[i][2] * inv_l; v.w = o[i][3] * inv_l;
            *(float4*)&g_O[((size_t)b * PN + n) * PE + h * 64 + 4 * tx] = v;
        }
        __syncthreads();
    }
#endif
    (void)Og;
}

// ---------------------------------------------------------------------------
extern "C" void kernel_launch(void* const* d_in, const int* in_sizes, int n_in,
                              void* d_out, int out_size)
{
    const float* x      = (const float*)d_in[0];
    const float* w_qkv  = (const float*)d_in[1];
    const float* b_qkv  = (const float*)d_in[2];
    const float* w_proj = (const float*)d_in[3];
    const float* b_proj = (const float*)d_in[4];
    float* out = (float*)d_out;

    cudaFuncSetAttribute(gemm_any<0>,
                         cudaFuncAttributeMaxDynamicSharedMemorySize, GEMM_SMEM);
    cudaFuncSetAttribute(gemm_any<1>,
                         cudaFuncAttributeMaxDynamicSharedMemorySize, GEMM_SMEM);
    cudaFuncSetAttribute(flash_attn,
                         cudaFuncAttributeMaxDynamicSharedMemorySize, FA_SMEM);

    float *xc, *wq, *wp, *Qp, *Kp, *Vp, *Op;
    cudaGetSymbolAddress((void**)&xc, g_xc);
    cudaGetSymbolAddress((void**)&wq, g_wq);
    cudaGetSymbolAddress((void**)&wp, g_wp);
    cudaGetSymbolAddress((void**)&Qp, g_Q);
    cudaGetSymbolAddress((void**)&Kp, g_K);
    cudaGetSymbolAddress((void**)&Vp, g_V);
    cudaGetSymbolAddress((void**)&Op, g_O);

    // 0) Pre-round inputs to tf32
    prep_convert<<<1024, 256>>>(x, w_qkv, w_proj);

    // 1) QKV projection + scatter (V stored transposed)
    {
        dim3 grid(QKV_COLS / 128, M_TOK / 128);
        gemm_any<0><<<grid, 256, GEMM_SMEM>>>(xc, wq, b_qkv, nullptr,
                                              QKV_COLS, PE);
    }

    // 2) Flash attention
    {
        dim3 grid(PN / 128, PB * PH);
        flash_attn<<<grid, 256, FA_SMEM>>>(Qp, Kp, Vp, Op);
    }

    // 3) Output projection
    {
        dim3 grid(PE / 128, M_TOK / 128);
        gemm_any<1><<<grid, 256, GEMM_SMEM>>>(Op, wp, b_proj, out,
                                              PE, PE);
    }
}